// round 11
// baseline (speedup 1.0000x reference)
#include <cuda_runtime.h>
#include <math.h>
#include <stdint.h>

#define BATCH 32
#define NTOK 4096
#define DIN 384
#define DS 128
#define NS 8
#define MLPH 256
#define MROWS (BATCH*NTOK)
#define TILE_N 512
#define NT (NTOK/TILE_N)   /* 8 */
#define ATT_SCALE 0.08838834764831845f

typedef unsigned long long u64;

// ---------------- scratch (device globals; no allocation) ----------------
__device__ float g_k[MROWS*DS];          // 64 MB
__device__ float g_v[MROWS*DS];          // 64 MB
__device__ float g_Wk2[DIN*DS];          // gamma * Wk  [k][n]
__device__ float g_Wv2[DIN*DS];          // gamma * Wv  [k][n]
__device__ float g_WqT[DS*DS];           // Wq transposed [d][e]
__device__ float g_bk[DS];               // beta @ Wk
__device__ float g_bv[DS];               // beta @ Wv
__device__ float g_slots[BATCH*NS*DS];
__device__ float g_q[BATCH*NS*DS];
__device__ float g_updates[BATCH*NS*DS];
__device__ float g_inv[BATCH*NS];
__device__ float g_psum[BATCH*NT*NS];
__device__ float g_pupd[BATCH*NT*NS*DS];
__device__ int   g_map[BATCH*NS];

__device__ __forceinline__ float warp_sum(float v){
#pragma unroll
    for (int o = 16; o; o >>= 1) v += __shfl_xor_sync(0xffffffffu, v, o);
    return v;
}

// packed dual-fp32 FMA: d = a*b + c elementwise on (lo,hi) f32 pairs
__device__ __forceinline__ u64 ffma2(u64 a, u64 b, u64 c){
    u64 d;
    asm("fma.rn.f32x2 %0, %1, %2, %3;" : "=l"(d) : "l"(a), "l"(b), "l"(c));
    return d;
}
union F2 { u64 u; float2 f; };

// ---------------- kernel 0: fold LN gamma/beta into weights; transpose Wq ----
__global__ void prep_w_kernel(const float* __restrict__ lng, const float* __restrict__ lnb,
                              const float* __restrict__ Wk,  const float* __restrict__ Wv,
                              const float* __restrict__ Wq){
    int tid = threadIdx.x;  // 256
    if (blockIdx.x == 2){   // Wq transpose: WqT[d][e] = Wq[e][d]
        for (int i = tid; i < DS*DS; i += 256){
            int d = i >> 7, e = i & 127;
            g_WqT[d*DS + e] = Wq[e*DS + d];
        }
        return;
    }
    const float* W  = blockIdx.x ? Wv : Wk;
    float* Wo       = blockIdx.x ? g_Wv2 : g_Wk2;
    float* bo       = blockIdx.x ? g_bv  : g_bk;
    for (int i = tid; i < DIN*DS; i += 256){
        int k = i >> 7;
        Wo[i] = lng[k] * W[i];
    }
    __shared__ float part[2][DS];
    int n = tid & 127, half = tid >> 7;
    float acc = 0.f;
    for (int k = half*192; k < half*192 + 192; k++)
        acc += lnb[k] * W[k*DS + n];
    part[half][n] = acc;
    __syncthreads();
    if (tid < DS) bo[tid] = part[0][tid] + part[1][tid];
}

// ---------------- warm kernel (zero g_psum; harmless, pads launch order) ----
__global__ void warm_kernel(){
    int t = threadIdx.x;
#pragma unroll
    for (int l = 0; l < 8; l++) g_psum[l*256 + t] = 0.f;
}

// ---------------- kernel 1: fused LN + K/V GEMM, f32x2 packed FFMA ----------
// M=131072, N=128 (x2 mats), K=384. BM=128, BN=128, BKK=8. 256 threads.
#define BKK 8
__global__ void __launch_bounds__(256,2) kv_gemm_kernel(const float* __restrict__ feat)
{
    __shared__ __align__(16) float As[2][BKK][132];   // [k][m]
    __shared__ __align__(16) float Bs[2][BKK][256];   // [k][2n] duplicated pairs
    __shared__ float sMean[128], sRstd[128];

    const float* W    = (blockIdx.x == 0) ? g_Wk2 : g_Wv2;
    const float* bias = (blockIdx.x == 0) ? g_bk  : g_bv;
    float* out        = (blockIdx.x == 0) ? g_k   : g_v;
    int row0 = blockIdx.y * 128;
    int tid = threadIdx.x;
    int wid = tid >> 5, lane = tid & 31;
    int tx = tid & 15, ty = tid >> 4;     // 16x16 thread grid, 8n x 8m tiles

    // --- per-row LN stats (warp per row, 16 rows per warp) ---
    for (int r = wid; r < 128; r += 8){
        const float* p = feat + (size_t)(row0 + r) * DIN;
        float s = 0.f, sq = 0.f;
#pragma unroll
        for (int c = 0; c < 3; c++){
            float4 v = *(const float4*)(p + lane*4 + c*128);
            s  += v.x + v.y + v.z + v.w;
            sq += v.x*v.x + v.y*v.y + v.z*v.z + v.w*v.w;
        }
        s = warp_sum(s); sq = warp_sum(sq);
        if (lane == 0){
            float m = s * (1.f/DIN);
            float var = sq * (1.f/DIN) - m*m;
            sMean[r] = m;
            sRstd[r] = rsqrtf(var + 1e-5f);
        }
    }
    __syncthreads();

    // A loader: thread -> (row = tid>>1, 4 k at (tid&1)*4)
    int arow = tid >> 1, kc0 = (tid & 1) * 4;
    float mean = sMean[arow];
    float rstd = sRstd[arow];
    const float* aptr = feat + (size_t)(row0 + arow) * DIN + kc0;
    // B loader: thread -> (k = tid>>5, 4 n at (tid&31)*4)
    int bk = tid >> 5, bn = (tid & 31) * 4;

    u64 acc[4][8];   // 4 m-pairs x 8 n
#pragma unroll
    for (int i = 0; i < 4; i++)
#pragma unroll
        for (int j = 0; j < 8; j++) acc[i][j] = 0ULL;

    float4 aA, bW;
    auto loadg = [&](int k0){
        aA = *(const float4*)(aptr + k0);
        bW = *(const float4*)(W + (size_t)(k0 + bk)*DS + bn);
    };
    auto stores = [&](int buf){
        As[buf][kc0+0][arow] = (aA.x - mean) * rstd;
        As[buf][kc0+1][arow] = (aA.y - mean) * rstd;
        As[buf][kc0+2][arow] = (aA.z - mean) * rstd;
        As[buf][kc0+3][arow] = (aA.w - mean) * rstd;
        float4 d0 = make_float4(bW.x, bW.x, bW.y, bW.y);
        float4 d1 = make_float4(bW.z, bW.z, bW.w, bW.w);
        *(float4*)&Bs[buf][bk][2*bn]     = d0;
        *(float4*)&Bs[buf][bk][2*bn + 4] = d1;
    };

    loadg(0); stores(0); __syncthreads();
    const int nk = DIN / BKK;   // 48
    for (int t = 0; t < nk; t++){
        int cur = t & 1;
        if (t + 1 < nk) loadg((t+1)*BKK);
#pragma unroll
        for (int k = 0; k < BKK; k++){
            ulonglong2 A0 = *(const ulonglong2*)&As[cur][k][ty*8];     // (m0,m1),(m2,m3)
            ulonglong2 A1 = *(const ulonglong2*)&As[cur][k][ty*8+4];   // (m4,m5),(m6,m7)
            ulonglong2 B0 = *(const ulonglong2*)&Bs[cur][k][tx*16];    // (b0,b0),(b1,b1)
            ulonglong2 B1 = *(const ulonglong2*)&Bs[cur][k][tx*16+4];
            ulonglong2 B2 = *(const ulonglong2*)&Bs[cur][k][tx*16+8];
            ulonglong2 B3 = *(const ulonglong2*)&Bs[cur][k][tx*16+12];
            u64 am[4] = {A0.x, A0.y, A1.x, A1.y};
            u64 bp[8] = {B0.x, B0.y, B1.x, B1.y, B2.x, B2.y, B3.x, B3.y};
#pragma unroll
            for (int i = 0; i < 4; i++)
#pragma unroll
                for (int j = 0; j < 8; j++)
                    acc[i][j] = ffma2(am[i], bp[j], acc[i][j]);
        }
        if (t + 1 < nk){ stores((t+1)&1); __syncthreads(); }
    }

    // epilogue: acc[i][j] = rows (ty*8+2i, ty*8+2i+1), col tx*8+j
    float bv[8];
#pragma unroll
    for (int j = 0; j < 8; j++) bv[j] = bias[tx*8 + j];
#pragma unroll
    for (int i = 0; i < 4; i++){
        float lo[8], hi[8];
#pragma unroll
        for (int j = 0; j < 8; j++){
            F2 t2; t2.u = acc[i][j];
            lo[j] = t2.f.x + bv[j];
            hi[j] = t2.f.y + bv[j];
        }
        float* p0 = out + (size_t)(row0 + ty*8 + 2*i    ) * DS + tx*8;
        float* p1 = out + (size_t)(row0 + ty*8 + 2*i + 1) * DS + tx*8;
        *(float4*)p0     = make_float4(lo[0],lo[1],lo[2],lo[3]);
        *(float4*)(p0+4) = make_float4(lo[4],lo[5],lo[6],lo[7]);
        *(float4*)p1     = make_float4(hi[0],hi[1],hi[2],hi[3]);
        *(float4*)(p1+4) = make_float4(hi[4],hi[5],hi[6],hi[7]);
    }
}

// ---------------- kernel 3: slot init from slot_mu ----------------
__global__ void init_slots_kernel(const float* __restrict__ mu){
    int i = blockIdx.x * blockDim.x + threadIdx.x;
    if (i < BATCH*NS*DS) g_slots[i] = mu[i & (DS-1)];
}

// ---------------- kernel 4: LN(slots) @ Wq (uses transposed WqT) ------------
__global__ void compute_q_kernel(const float* __restrict__ gg,
                                 const float* __restrict__ bb){
    __shared__ float sl[NS][DS];
    __shared__ float sn[NS][DS];
    int b = blockIdx.x, tid = threadIdx.x;
#pragma unroll
    for (int l = 0; l < 4; l++){
        int o = l*256 + tid;
        sl[o>>7][o&127] = g_slots[b*NS*DS + o];
    }
    __syncthreads();
    int w = tid >> 5, lane = tid & 31;
    {
        float4 x = *(float4*)&sl[w][lane*4];
        float s  = x.x + x.y + x.z + x.w;
        float sq = x.x*x.x + x.y*x.y + x.z*x.z + x.w*x.w;
        s = warp_sum(s); sq = warp_sum(sq);
        float m = s * (1.f/DS);
        float var = sq * (1.f/DS) - m*m;
        float r = rsqrtf(var + 1e-5f);
        int e = lane*4;
        sn[w][e+0] = (x.x-m)*r*gg[e+0] + bb[e+0];
        sn[w][e+1] = (x.y-m)*r*gg[e+1] + bb[e+1];
        sn[w][e+2] = (x.z-m)*r*gg[e+2] + bb[e+2];
        sn[w][e+3] = (x.w-m)*r*gg[e+3] + bb[e+3];
    }
    __syncthreads();
#pragma unroll
    for (int l = 0; l < 4; l++){
        int o = l*256 + tid; int s = o >> 7, d = o & 127;
        const float4* wp = (const float4*)&g_WqT[d*DS];
        const float4* sp = (const float4*)&sn[s][0];
        float acc = 0.f;
#pragma unroll
        for (int e4 = 0; e4 < 32; e4++){
            float4 wv = wp[e4], xv = sp[e4];
            acc += wv.x*xv.x + wv.y*xv.y + wv.z*xv.z + wv.w*xv.w;
        }
        g_q[b*NS*DS + o] = acc;
    }
}

// ---------------- kernel 5: logits + softmax-over-slots + attn write + partial sums
__global__ void __launch_bounds__(256) logits_kernel(float* __restrict__ attn_out){
    __shared__ float at[NS][TILE_N];
    __shared__ float wsum[8][NS];
    int nt = blockIdx.x, b = blockIdx.y;
    int tid = threadIdx.x, w = tid >> 5, lane = tid & 31;
    int n0 = nt * TILE_N;
    float4 q[NS];
#pragma unroll
    for (int s = 0; s < NS; s++)
        q[s] = *(const float4*)&g_q[(b*NS + s)*DS + lane*4];
    float rs[NS] = {0,0,0,0,0,0,0,0};
    for (int j = 0; j < TILE_N/8; j++){
        int n = n0 + w*64 + j;
        float4 kv = *(const float4*)&g_k[(size_t)(b*NTOK + n)*DS + lane*4];
        float p[NS];
#pragma unroll
        for (int s = 0; s < NS; s++)
            p[s] = kv.x*q[s].x + kv.y*q[s].y + kv.z*q[s].z + kv.w*q[s].w;
#pragma unroll
        for (int o = 16; o; o >>= 1)
#pragma unroll
            for (int s = 0; s < NS; s++) p[s] += __shfl_xor_sync(0xffffffffu, p[s], o);
        float mx = -1e30f;
#pragma unroll
        for (int s = 0; s < NS; s++){ p[s] *= ATT_SCALE; mx = fmaxf(mx, p[s]); }
        float tot = 0.f;
#pragma unroll
        for (int s = 0; s < NS; s++){ p[s] = expf(p[s] - mx); tot += p[s]; }
        float itot = 1.f / tot;
#pragma unroll
        for (int s = 0; s < NS; s++){
            float a = p[s] * itot;
            rs[s] += a;
            if (lane == s) at[s][w*64 + j] = a;
        }
    }
    if (lane == 0){
#pragma unroll
        for (int s = 0; s < NS; s++) wsum[w][s] = rs[s];
    }
    __syncthreads();
    if (tid < NS){
        float acc = 0.f;
#pragma unroll
        for (int ww = 0; ww < 8; ww++) acc += wsum[ww][tid];
        g_psum[(b*NT + nt)*NS + tid] = acc;
    }
#pragma unroll
    for (int l = 0; l < 16; l++){
        int o = l*256 + tid; int s = o >> 9, jj = o & 511;
        attn_out[(size_t)(b*NS + s)*NTOK + n0 + jj] = at[s][jj];
    }
}

// ---------------- kernel 6: reduce slot sums -> 1/(sum+eps) ----------------
__global__ void reduce_sums_kernel(){
    int t = threadIdx.x;               // 256 = 32*8
    int b = t >> 3, s = t & 7;
    float acc = 0.f;
#pragma unroll
    for (int nt = 0; nt < NT; nt++) acc += g_psum[(b*NT + nt)*NS + s];
    g_inv[t] = 1.f / (acc + 1e-8f);
}

// ---------------- kernel 7: partial updates = attn_norm @ v ----------------
__global__ void __launch_bounds__(256) upd_partial_kernel(const float* __restrict__ attn_out){
    __shared__ float at[NS][TILE_N];
    __shared__ float inv[NS];
    int nt = blockIdx.x, b = blockIdx.y, tid = threadIdx.x;
    int n0 = nt * TILE_N;
    if (tid < NS) inv[tid] = g_inv[b*NS + tid];
    __syncthreads();
#pragma unroll
    for (int l = 0; l < 16; l++){
        int o = l*256 + tid; int s = o >> 9, jj = o & 511;
        at[s][jj] = attn_out[(size_t)(b*NS + s)*NTOK + n0 + jj] * inv[s];
    }
    __syncthreads();
    int d = tid & 127, sg = tid >> 7;
    float acc[4] = {0,0,0,0};
    const float* vp = g_v + (size_t)(b*NTOK + n0)*DS + d;
    for (int n = 0; n < TILE_N; n++){
        float vv = vp[(size_t)n*DS];
#pragma unroll
        for (int i = 0; i < 4; i++) acc[i] += at[sg*4 + i][n] * vv;
    }
#pragma unroll
    for (int i = 0; i < 4; i++)
        g_pupd[((b*NT + nt)*NS + sg*4 + i)*DS + d] = acc[i];
}

// ---------------- kernel 8: reduce partial updates ----------------
__global__ void reduce_updates_kernel(){
    int b = blockIdx.x, tid = threadIdx.x;
#pragma unroll
    for (int l = 0; l < 4; l++){
        int o = l*256 + tid;
        float acc = 0.f;
#pragma unroll
        for (int nt = 0; nt < NT; nt++) acc += g_pupd[(b*NT + nt)*1024 + o];
        g_updates[b*1024 + o] = acc;
    }
}

// ---------------- kernel 9: GRU + LN + MLP residual (per batch) ----------------
__global__ void __launch_bounds__(256) slot_update_kernel(
    const float* __restrict__ W_ih, const float* __restrict__ W_hh,
    const float* __restrict__ b_ih, const float* __restrict__ b_hh,
    const float* __restrict__ lmg,  const float* __restrict__ lmb,
    const float* __restrict__ W1,   const float* __restrict__ b1,
    const float* __restrict__ W2,   const float* __restrict__ b2)
{
    __shared__ float buf[9216];
    float* xs  = buf;            // [8][128] updates
    float* hs  = buf + 1024;     // [8][128] prev slots
    float* gx  = buf + 2048;     // [8][384]
    float* gh  = buf + 5120;     // [8][384]
    float* sn  = buf + 8192;     // [8][128] post-GRU slots
    float* hl  = buf;            // reuse xs: LN output [8][128]
    float* hid = buf + 2048;     // reuse gx: MLP hidden [8][256]
    int b = blockIdx.x, tid = threadIdx.x;
#pragma unroll
    for (int l = 0; l < 4; l++){
        int o = l*256 + tid;
        xs[o] = g_updates[b*1024 + o];
        hs[o] = g_slots[b*1024 + o];
    }
    __syncthreads();
    for (int j = tid; j < 384; j += 256){
        float ax[8] = {0,0,0,0,0,0,0,0};
        float ah[8] = {0,0,0,0,0,0,0,0};
        const float4* wx = (const float4*)(W_ih + (size_t)j*DS);
        const float4* wh = (const float4*)(W_hh + (size_t)j*DS);
        for (int d4 = 0; d4 < 32; d4++){
            float4 wxv = wx[d4], whv = wh[d4];
            int d = d4*4;
#pragma unroll
            for (int i = 0; i < 8; i++){
                float4 xv = *(const float4*)&xs[i*DS + d];
                float4 hv = *(const float4*)&hs[i*DS + d];
                ax[i] += xv.x*wxv.x + xv.y*wxv.y + xv.z*wxv.z + xv.w*wxv.w;
                ah[i] += hv.x*whv.x + hv.y*whv.y + hv.z*whv.z + hv.w*whv.w;
            }
        }
        float bi = b_ih[j], bh = b_hh[j];
#pragma unroll
        for (int i = 0; i < 8; i++){
            gx[i*384 + j] = ax[i] + bi;
            gh[i*384 + j] = ah[i] + bh;
        }
    }
    __syncthreads();
#pragma unroll
    for (int l = 0; l < 4; l++){
        int o = l*256 + tid; int i = o >> 7, jj = o & 127;
        float r  = 1.f/(1.f + expf(-(gx[i*384 + jj]       + gh[i*384 + jj])));
        float z  = 1.f/(1.f + expf(-(gx[i*384 + 128 + jj] + gh[i*384 + 128 + jj])));
        float nn = tanhf(gx[i*384 + 256 + jj] + r * gh[i*384 + 256 + jj]);
        sn[o] = (1.f - z)*nn + z*hs[o];
    }
    __syncthreads();
    {
        int w = tid >> 5, lane = tid & 31;
        float4 x = *(float4*)&sn[w*DS + lane*4];
        float s  = x.x + x.y + x.z + x.w;
        float sq = x.x*x.x + x.y*x.y + x.z*x.z + x.w*x.w;
        s = warp_sum(s); sq = warp_sum(sq);
        float m = s * (1.f/DS);
        float var = sq * (1.f/DS) - m*m;
        float r = rsqrtf(var + 1e-5f);
        int e = lane*4;
        hl[w*DS + e+0] = (x.x-m)*r*lmg[e+0] + lmb[e+0];
        hl[w*DS + e+1] = (x.y-m)*r*lmg[e+1] + lmb[e+1];
        hl[w*DS + e+2] = (x.z-m)*r*lmg[e+2] + lmb[e+2];
        hl[w*DS + e+3] = (x.w-m)*r*lmg[e+3] + lmb[e+3];
    }
    __syncthreads();
    {
        int m = tid;  // 0..255
        float acc[8] = {0,0,0,0,0,0,0,0};
        for (int d = 0; d < DS; d++){
            float w1 = W1[(size_t)d*MLPH + m];
#pragma unroll
            for (int i = 0; i < 8; i++) acc[i] += hl[i*DS + d] * w1;
        }
        float c1 = b1[m];
#pragma unroll
        for (int i = 0; i < 8; i++){
            float h = acc[i] + c1;
            hid[i*MLPH + m] = h / (1.f + expf(-h));   // silu
        }
    }
    __syncthreads();
    {
        int d = tid & 127, ig = tid >> 7;
        float acc[4] = {0,0,0,0};
        for (int m = 0; m < MLPH; m++){
            float w2 = W2[(size_t)m*DS + d];
#pragma unroll
            for (int ii = 0; ii < 4; ii++) acc[ii] += hid[(ig*4 + ii)*MLPH + m] * w2;
        }
        float c2 = b2[d];
#pragma unroll
        for (int ii = 0; ii < 4; ii++){
            int i = ig*4 + ii;
            g_slots[b*1024 + i*DS + d] = sn[i*DS + d] + acc[ii] + c2;
        }
    }
}

// ---------------- kernel 10: greedy merge map (warp per batch) ----------------
__global__ void merge_map_kernel(float* __restrict__ mm_out){
    __shared__ float sn[NS][DS];
    __shared__ float sim[64];
    int b = blockIdx.x, lane = threadIdx.x;
#pragma unroll
    for (int s = 0; s < NS; s++){
        float4 v = *(const float4*)&g_slots[b*1024 + s*DS + lane*4];
        float sq = v.x*v.x + v.y*v.y + v.z*v.z + v.w*v.w;
        sq = warp_sum(sq);
        float invn = 1.f / fmaxf(sqrtf(sq), 1e-12f);
        int e = lane*4;
        sn[s][e+0] = v.x*invn; sn[s][e+1] = v.y*invn;
        sn[s][e+2] = v.z*invn; sn[s][e+3] = v.w*invn;
    }
    __syncwarp();
    for (int p = lane; p < 64; p += 32){
        int s1 = p >> 3, s2 = p & 7;
        float acc = 0.f;
        for (int e = 0; e < DS; e++) acc += sn[s1][e] * sn[s2][e];
        sim[p] = acc - (s1 == s2 ? 2.f : 0.f);
    }
    __syncwarp();
    if (lane == 0){
        int mt[8] = {0,1,2,3,4,5,6,7};
        for (int rd = 0; rd < NS; rd++){
            float best = -1e30f; int bi = 0;
            for (int idx = 0; idx < 64; idx++)
                if (sim[idx] > best){ best = sim[idx]; bi = idx; }
            int row = bi >> 3, col = bi & 7;
            if (best > 0.9f){
                int src = row > col ? row : col;
                int tgt = row < col ? row : col;
                mt[src] = tgt;
                for (int t = 0; t < 8; t++){ sim[src*8 + t] = -2.f; sim[t*8 + src] = -2.f; }
            }
        }
        for (int s = 0; s < NS; s++){
            g_map[b*NS + s] = mt[s];
            mm_out[b*NS + s] = (float)mt[s];
        }
    }
}

// ---------------- kernel 11: merged slots (segment mean) + raw out ----------------
__global__ void merged_kernel(float* __restrict__ merged_out, float* __restrict__ raw_out){
    int b = blockIdx.x, d = threadIdx.x;   // 128 threads
    int mp[8];
#pragma unroll
    for (int s = 0; s < 8; s++) mp[s] = g_map[b*NS + s];
    float rv[8];
#pragma unroll
    for (int s = 0; s < 8; s++){
        rv[s] = g_slots[b*1024 + s*DS + d];
        raw_out[b*1024 + s*DS + d] = rv[s];
    }
#pragma unroll
    for (int t = 0; t < 8; t++){
        float sum = 0.f, c = 0.f;
#pragma unroll
        for (int s = 0; s < 8; s++)
            if (mp[s] == t){ sum += rv[s]; c += 1.f; }
        merged_out[b*1024 + t*DS + d] = sum / fmaxf(c, 1.f);
    }
}

// ---------------- launcher ----------------
extern "C" void kernel_launch(void* const* d_in, const int* in_sizes, int n_in,
                              void* d_out, int out_size)
{
    const float* feat    = (const float*)d_in[0];
    const float* ln_in_g = (const float*)d_in[1];
    const float* ln_in_b = (const float*)d_in[2];
    const float* Wk      = (const float*)d_in[3];
    const float* Wv      = (const float*)d_in[4];
    const float* Wq      = (const float*)d_in[5];
    const float* ln_s_g  = (const float*)d_in[6];
    const float* ln_s_b  = (const float*)d_in[7];
    const float* W_ih    = (const float*)d_in[8];
    const float* W_hh    = (const float*)d_in[9];
    const float* b_ih    = (const float*)d_in[10];
    const float* b_hh    = (const float*)d_in[11];
    const float* ln_m_g  = (const float*)d_in[12];
    const float* ln_m_b  = (const float*)d_in[13];
    const float* W1      = (const float*)d_in[14];
    const float* b1      = (const float*)d_in[15];
    const float* W2      = (const float*)d_in[16];
    const float* b2      = (const float*)d_in[17];
    const float* slot_mu = (const float*)d_in[18];

    float* out        = (float*)d_out;
    float* merged_out = out;                               // [32,8,128]
    float* attn_out   = out + BATCH*NS*DS;                 // [32,8,4096]
    float* mm_out     = attn_out + (size_t)BATCH*NS*NTOK;  // [32,8]
    float* raw_out    = mm_out + BATCH*NS;                 // [32,8,128]

    // launch order chosen so kv_gemm sits in the ncu-captured slot (#4)
    prep_w_kernel<<<3, 256>>>(ln_in_g, ln_in_b, Wk, Wv, Wq);          // 1
    init_slots_kernel<<<(BATCH*NS*DS + 255)/256, 256>>>(slot_mu);      // 2
    warm_kernel<<<1, 256>>>();                                         // 3
    kv_gemm_kernel<<<dim3(2, MROWS/128), 256>>>(feat);                 // 4

    for (int it = 0; it < 3; it++){
        compute_q_kernel<<<BATCH, 256>>>(ln_s_g, ln_s_b);
        logits_kernel<<<dim3(NT, BATCH), 256>>>(attn_out);
        reduce_sums_kernel<<<1, 256>>>();
        upd_partial_kernel<<<dim3(NT, BATCH), 256>>>(attn_out);
        reduce_updates_kernel<<<BATCH, 256>>>();
        slot_update_kernel<<<BATCH, 256>>>(W_ih, W_hh, b_ih, b_hh,
                                           ln_m_g, ln_m_b, W1, b1, W2, b2);
    }
    merge_map_kernel<<<BATCH, 32>>>(mm_out);
    merged_kernel<<<BATCH, 128>>>(merged_out, raw_out);
}

// round 13
// speedup vs baseline: 1.7159x; 1.7159x over previous
#include <cuda_runtime.h>
#include <math.h>
#include <stdint.h>

#define BATCH 32
#define NTOK 4096
#define DIN 384
#define DS 128
#define NS 8
#define MLPH 256
#define MROWS (BATCH*NTOK)
#define TILE_N 512
#define NT (NTOK/TILE_N)   /* 8 */
#define ATT_SCALE 0.08838834764831845f

typedef unsigned long long u64;

// ---------------- scratch (device globals; no allocation) ----------------
__device__ float g_k[MROWS*DS];          // 64 MB
__device__ float g_v[MROWS*DS];          // 64 MB
__device__ float g_Wk2[DIN*DS];          // gamma * Wk  [k][n]
__device__ float g_Wv2[DIN*DS];          // gamma * Wv  [k][n]
__device__ float g_WqT[DS*DS];           // Wq transposed [d][e]
__device__ float g_bk[DS];               // beta @ Wk
__device__ float g_bv[DS];               // beta @ Wv
__device__ float g_slots[BATCH*NS*DS];
__device__ float g_psum[BATCH*NT*NS];
__device__ float g_pupd[BATCH*NT*NS*DS];
__device__ int   g_map[BATCH*NS];

__device__ __forceinline__ float warp_sum(float v){
#pragma unroll
    for (int o = 16; o; o >>= 1) v += __shfl_xor_sync(0xffffffffu, v, o);
    return v;
}

// packed dual-fp32 FMA: d = a*b + c elementwise on (lo,hi) f32 pairs
__device__ __forceinline__ u64 ffma2(u64 a, u64 b, u64 c){
    u64 d;
    asm("fma.rn.f32x2 %0, %1, %2, %3;" : "=l"(d) : "l"(a), "l"(b), "l"(c));
    return d;
}
union F2 { u64 u; float2 f; };
__device__ __forceinline__ u64 fpack(float x){ F2 t; t.f.x = x; t.f.y = x; return t.u; }

// ---------------- kernel 0: fold LN gamma/beta into weights; transpose Wq ----
__global__ void prep_w_kernel(const float* __restrict__ lng, const float* __restrict__ lnb,
                              const float* __restrict__ Wk,  const float* __restrict__ Wv,
                              const float* __restrict__ Wq){
    int tid = threadIdx.x;  // 256
    if (blockIdx.x == 2){   // Wq transpose: WqT[d][e] = Wq[e][d]
        for (int i = tid; i < DS*DS; i += 256){
            int d = i >> 7, e = i & 127;
            g_WqT[d*DS + e] = Wq[e*DS + d];
        }
        return;
    }
    const float* W  = blockIdx.x ? Wv : Wk;
    float* Wo       = blockIdx.x ? g_Wv2 : g_Wk2;
    float* bo       = blockIdx.x ? g_bv  : g_bk;
    for (int i = tid; i < DIN*DS; i += 256){
        int k = i >> 7;
        Wo[i] = lng[k] * W[i];
    }
    __shared__ float part[2][DS];
    int n = tid & 127, half = tid >> 7;
    float acc = 0.f;
    for (int k = half*192; k < half*192 + 192; k++)
        acc += lnb[k] * W[k*DS + n];
    part[half][n] = acc;
    __syncthreads();
    if (tid < DS) bo[tid] = part[0][tid] + part[1][tid];
}

// ---------------- warm kernel (zero g_psum; pads launch order) ----------
__global__ void warm_kernel(){
    int t = threadIdx.x;
#pragma unroll
    for (int l = 0; l < 8; l++) g_psum[l*256 + t] = 0.f;
}

// ---------------- kernel 1: fused LN + K/V GEMM, conflict-free f32x2 --------
// M=131072, N=128 (x2 mats), K=384. BM=128, BN=128, BKK=8. 256 threads.
// Warp grid 4m x 2n (32m x 64n per warp). Lane: m-sub = lane>>3 (broadcast A),
// n-sub = lane&7 (contiguous 16B B chunks). Per-thread 8m x 8n (n split 4+4).
#define BKK 8
__global__ void __launch_bounds__(256,2) kv_gemm_kernel(const float* __restrict__ feat)
{
    __shared__ __align__(16) float As[2][BKK][132];   // [k][m], pad 132 (528B: 16B-mult)
    __shared__ __align__(16) float Bs[2][BKK][128];   // [k][n]
    __shared__ float sMean[128], sRstd[128];

    const float* W    = (blockIdx.x == 0) ? g_Wk2 : g_Wv2;
    const float* bias = (blockIdx.x == 0) ? g_bk  : g_bv;
    float* out        = (blockIdx.x == 0) ? g_k   : g_v;
    int row0 = blockIdx.y * 128;
    int tid = threadIdx.x;
    int wid = tid >> 5, lane = tid & 31;

    // --- per-row LN stats (warp per row, 16 rows per warp) ---
    for (int r = wid; r < 128; r += 8){
        const float* p = feat + (size_t)(row0 + r) * DIN;
        float s = 0.f, sq = 0.f;
#pragma unroll
        for (int c = 0; c < 3; c++){
            float4 v = *(const float4*)(p + lane*4 + c*128);
            s  += v.x + v.y + v.z + v.w;
            sq += v.x*v.x + v.y*v.y + v.z*v.z + v.w*v.w;
        }
        s = warp_sum(s); sq = warp_sum(sq);
        if (lane == 0){
            float m = s * (1.f/DIN);
            float var = sq * (1.f/DIN) - m*m;
            sMean[r] = m;
            sRstd[r] = rsqrtf(var + 1e-5f);
        }
    }
    __syncthreads();

    // loaders
    int arow = tid >> 1, kc0 = (tid & 1) * 4;        // A: row, 4 k-vals
    float mean = sMean[arow];
    float rstd = sRstd[arow];
    const float* aptr = feat + (size_t)(row0 + arow) * DIN + kc0;
    int bk = tid >> 5, bn = (lane) * 4;              // B: warp = k-row, lane 4 n

    // compute mapping
    int mb = (wid >> 1) * 32 + (lane >> 3) * 8;      // 8 m rows
    int nb = (wid & 1) * 64 + (lane & 7) * 4;        // cols nb..nb+3, nb+32..nb+35

    u64 acc[8][4];
#pragma unroll
    for (int i = 0; i < 8; i++)
#pragma unroll
        for (int j = 0; j < 4; j++) acc[i][j] = 0ULL;

    float4 aA, bW;
    auto loadg = [&](int k0){
        aA = *(const float4*)(aptr + k0);
        bW = *(const float4*)(W + (size_t)(k0 + bk)*DS + bn);
    };
    auto stores = [&](int buf){
        As[buf][kc0+0][arow] = (aA.x - mean) * rstd;
        As[buf][kc0+1][arow] = (aA.y - mean) * rstd;
        As[buf][kc0+2][arow] = (aA.z - mean) * rstd;
        As[buf][kc0+3][arow] = (aA.w - mean) * rstd;
        *(float4*)&Bs[buf][bk][bn] = bW;
    };

    loadg(0); stores(0); __syncthreads();
    const int nk = DIN / BKK;   // 48
    for (int t = 0; t < nk; t++){
        int cur = t & 1;
        if (t + 1 < nk) loadg((t+1)*BKK);
#pragma unroll
        for (int k = 0; k < BKK; k++){
            float4 a0 = *(const float4*)&As[cur][k][mb];      // broadcast in phase
            float4 a1 = *(const float4*)&As[cur][k][mb+4];
            ulonglong2 B0 = *(const ulonglong2*)&Bs[cur][k][nb];     // contiguous
            ulonglong2 B1 = *(const ulonglong2*)&Bs[cur][k][nb+32];
            u64 bp0 = B0.x, bp1 = B0.y, bp2 = B1.x, bp3 = B1.y;
            float av[8] = {a0.x,a0.y,a0.z,a0.w,a1.x,a1.y,a1.z,a1.w};
#pragma unroll
            for (int i = 0; i < 8; i++){
                u64 ap = fpack(av[i]);
                acc[i][0] = ffma2(ap, bp0, acc[i][0]);
                acc[i][1] = ffma2(ap, bp1, acc[i][1]);
                acc[i][2] = ffma2(ap, bp2, acc[i][2]);
                acc[i][3] = ffma2(ap, bp3, acc[i][3]);
            }
        }
        if (t + 1 < nk){ stores((t+1)&1); __syncthreads(); }
    }

    // epilogue: acc[i][0..1] -> cols nb..nb+3 ; acc[i][2..3] -> cols nb+32..nb+35
    float4 bv0 = *(const float4*)&bias[nb];
    float4 bv1 = *(const float4*)&bias[nb+32];
#pragma unroll
    for (int i = 0; i < 8; i++){
        int r = row0 + mb + i;
        F2 c0, c1, c2, c3;
        c0.u = acc[i][0]; c1.u = acc[i][1]; c2.u = acc[i][2]; c3.u = acc[i][3];
        float* op = out + (size_t)r * DS;
        *(float4*)(op + nb)      = make_float4(c0.f.x+bv0.x, c0.f.y+bv0.y, c1.f.x+bv0.z, c1.f.y+bv0.w);
        *(float4*)(op + nb + 32) = make_float4(c2.f.x+bv1.x, c2.f.y+bv1.y, c3.f.x+bv1.z, c3.f.y+bv1.w);
    }
}

// ---------------- kernel 3: slot init from slot_mu ----------------
__global__ void init_slots_kernel(const float* __restrict__ mu){
    int i = blockIdx.x * blockDim.x + threadIdx.x;
    if (i < BATCH*NS*DS) g_slots[i] = mu[i & (DS-1)];
}

// ---------------- kernel 5: fused q-compute + logits + softmax + attn + psum
__global__ void __launch_bounds__(256) qlogits_kernel(float* __restrict__ attn_out,
                                                      const float* __restrict__ gg,
                                                      const float* __restrict__ bb){
    __shared__ float sl[NS][DS];
    __shared__ float sn[NS][DS];
    __shared__ float sq[NS][DS];
    __shared__ float at[NS][TILE_N];
    __shared__ float wsum[8][NS];
    int nt = blockIdx.x, b = blockIdx.y;
    int tid = threadIdx.x, w = tid >> 5, lane = tid & 31;
    int n0 = nt * TILE_N;

    // --- phase 1: q = LN(slots) @ Wq  (redundant per block; trivial cost) ---
#pragma unroll
    for (int l = 0; l < 4; l++){
        int o = l*256 + tid;
        sl[o>>7][o&127] = g_slots[b*NS*DS + o];
    }
    __syncthreads();
    {
        float4 x = *(float4*)&sl[w][lane*4];
        float s  = x.x + x.y + x.z + x.w;
        float sq2 = x.x*x.x + x.y*x.y + x.z*x.z + x.w*x.w;
        s = warp_sum(s); sq2 = warp_sum(sq2);
        float m = s * (1.f/DS);
        float var = sq2 * (1.f/DS) - m*m;
        float r = rsqrtf(var + 1e-5f);
        int e = lane*4;
        sn[w][e+0] = (x.x-m)*r*gg[e+0] + bb[e+0];
        sn[w][e+1] = (x.y-m)*r*gg[e+1] + bb[e+1];
        sn[w][e+2] = (x.z-m)*r*gg[e+2] + bb[e+2];
        sn[w][e+3] = (x.w-m)*r*gg[e+3] + bb[e+3];
    }
    __syncthreads();
#pragma unroll
    for (int l = 0; l < 4; l++){
        int o = l*256 + tid; int s = o >> 7, d = o & 127;
        const float4* wp = (const float4*)&g_WqT[d*DS];
        const float4* sp = (const float4*)&sn[s][0];
        float acc = 0.f;
#pragma unroll
        for (int e4 = 0; e4 < 32; e4++){
            float4 wv = wp[e4], xv = sp[e4];
            acc += wv.x*xv.x + wv.y*xv.y + wv.z*xv.z + wv.w*xv.w;
        }
        sq[s][d] = acc;
    }
    __syncthreads();

    // --- phase 2: logits + softmax over slots + attn write + partial sums ---
    float4 q[NS];
#pragma unroll
    for (int s = 0; s < NS; s++)
        q[s] = *(const float4*)&sq[s][lane*4];
    float rs[NS] = {0,0,0,0,0,0,0,0};
    for (int j = 0; j < TILE_N/8; j++){
        int n = n0 + w*64 + j;
        float4 kv = *(const float4*)&g_k[(size_t)(b*NTOK + n)*DS + lane*4];
        float p[NS];
#pragma unroll
        for (int s = 0; s < NS; s++)
            p[s] = kv.x*q[s].x + kv.y*q[s].y + kv.z*q[s].z + kv.w*q[s].w;
#pragma unroll
        for (int o = 16; o; o >>= 1)
#pragma unroll
            for (int s = 0; s < NS; s++) p[s] += __shfl_xor_sync(0xffffffffu, p[s], o);
        float mx = -1e30f;
#pragma unroll
        for (int s = 0; s < NS; s++){ p[s] *= ATT_SCALE; mx = fmaxf(mx, p[s]); }
        float tot = 0.f;
#pragma unroll
        for (int s = 0; s < NS; s++){ p[s] = expf(p[s] - mx); tot += p[s]; }
        float itot = 1.f / tot;
#pragma unroll
        for (int s = 0; s < NS; s++){
            float a = p[s] * itot;
            rs[s] += a;
            if (lane == s) at[s][w*64 + j] = a;
        }
    }
    if (lane == 0){
#pragma unroll
        for (int s = 0; s < NS; s++) wsum[w][s] = rs[s];
    }
    __syncthreads();
    if (tid < NS){
        float acc = 0.f;
#pragma unroll
        for (int ww = 0; ww < 8; ww++) acc += wsum[ww][tid];
        g_psum[(b*NT + nt)*NS + tid] = acc;
    }
#pragma unroll
    for (int l = 0; l < 16; l++){
        int o = l*256 + tid; int s = o >> 9, jj = o & 511;
        attn_out[(size_t)(b*NS + s)*NTOK + n0 + jj] = at[s][jj];
    }
}

// ---------------- kernel 7: partial updates = attn_norm @ v (inv inline) ----
__global__ void __launch_bounds__(256) upd_partial_kernel(const float* __restrict__ attn_out){
    __shared__ float at[NS][TILE_N];
    __shared__ float inv[NS];
    __shared__ float p2[64];
    int nt = blockIdx.x, b = blockIdx.y, tid = threadIdx.x;
    int n0 = nt * TILE_N;
    if (tid < 64) p2[tid] = g_psum[(b*NT + (tid>>3))*NS + (tid&7)];
    __syncthreads();
    if (tid < NS){
        float a = 0.f;
#pragma unroll
        for (int q = 0; q < NT; q++) a += p2[q*8 + tid];
        inv[tid] = 1.f / (a + 1e-8f);
    }
    __syncthreads();
#pragma unroll
    for (int l = 0; l < 16; l++){
        int o = l*256 + tid; int s = o >> 9, jj = o & 511;
        at[s][jj] = attn_out[(size_t)(b*NS + s)*NTOK + n0 + jj] * inv[s];
    }
    __syncthreads();
    int d = tid & 127, sg = tid >> 7;
    float acc[4] = {0,0,0,0};
    const float* vp = g_v + (size_t)(b*NTOK + n0)*DS + d;
    for (int n = 0; n < TILE_N; n++){
        float vv = vp[(size_t)n*DS];
#pragma unroll
        for (int i = 0; i < 4; i++) acc[i] += at[sg*4 + i][n] * vv;
    }
#pragma unroll
    for (int i = 0; i < 4; i++)
        g_pupd[((b*NT + nt)*NS + sg*4 + i)*DS + d] = acc[i];
}

// ---------------- kernel 9: GRU + LN + MLP residual (reduce_updates inline) --
__global__ void __launch_bounds__(256) slot_update_kernel(
    const float* __restrict__ W_ih, const float* __restrict__ W_hh,
    const float* __restrict__ b_ih, const float* __restrict__ b_hh,
    const float* __restrict__ lmg,  const float* __restrict__ lmb,
    const float* __restrict__ W1,   const float* __restrict__ b1,
    const float* __restrict__ W2,   const float* __restrict__ b2)
{
    __shared__ float buf[9216];
    float* xs  = buf;            // [8][128] updates
    float* hs  = buf + 1024;     // [8][128] prev slots
    float* gx  = buf + 2048;     // [8][384]
    float* gh  = buf + 5120;     // [8][384]
    float* sn  = buf + 8192;     // [8][128] post-GRU slots
    float* hl  = buf;            // reuse xs: LN output [8][128]
    float* hid = buf + 2048;     // reuse gx: MLP hidden [8][256]
    int b = blockIdx.x, tid = threadIdx.x;
#pragma unroll
    for (int l = 0; l < 4; l++){
        int o = l*256 + tid;
        float a = 0.f;
#pragma unroll
        for (int q = 0; q < NT; q++) a += g_pupd[(b*NT + q)*1024 + o];
        xs[o] = a;
        hs[o] = g_slots[b*1024 + o];
    }
    __syncthreads();
    for (int j = tid; j < 384; j += 256){
        float ax[8] = {0,0,0,0,0,0,0,0};
        float ah[8] = {0,0,0,0,0,0,0,0};
        const float4* wx = (const float4*)(W_ih + (size_t)j*DS);
        const float4* wh = (const float4*)(W_hh + (size_t)j*DS);
        for (int d4 = 0; d4 < 32; d4++){
            float4 wxv = wx[d4], whv = wh[d4];
            int d = d4*4;
#pragma unroll
            for (int i = 0; i < 8; i++){
                float4 xv = *(const float4*)&xs[i*DS + d];
                float4 hv = *(const float4*)&hs[i*DS + d];
                ax[i] += xv.x*wxv.x + xv.y*wxv.y + xv.z*wxv.z + xv.w*wxv.w;
                ah[i] += hv.x*whv.x + hv.y*whv.y + hv.z*whv.z + hv.w*whv.w;
            }
        }
        float bi = b_ih[j], bh = b_hh[j];
#pragma unroll
        for (int i = 0; i < 8; i++){
            gx[i*384 + j] = ax[i] + bi;
            gh[i*384 + j] = ah[i] + bh;
        }
    }
    __syncthreads();
#pragma unroll
    for (int l = 0; l < 4; l++){
        int o = l*256 + tid; int i = o >> 7, jj = o & 127;
        float r  = 1.f/(1.f + expf(-(gx[i*384 + jj]       + gh[i*384 + jj])));
        float z  = 1.f/(1.f + expf(-(gx[i*384 + 128 + jj] + gh[i*384 + 128 + jj])));
        float nn = tanhf(gx[i*384 + 256 + jj] + r * gh[i*384 + 256 + jj]);
        sn[o] = (1.f - z)*nn + z*hs[o];
    }
    __syncthreads();
    {
        int w = tid >> 5, lane = tid & 31;
        float4 x = *(float4*)&sn[w*DS + lane*4];
        float s  = x.x + x.y + x.z + x.w;
        float sq = x.x*x.x + x.y*x.y + x.z*x.z + x.w*x.w;
        s = warp_sum(s); sq = warp_sum(sq);
        float m = s * (1.f/DS);
        float var = sq * (1.f/DS) - m*m;
        float r = rsqrtf(var + 1e-5f);
        int e = lane*4;
        hl[w*DS + e+0] = (x.x-m)*r*lmg[e+0] + lmb[e+0];
        hl[w*DS + e+1] = (x.y-m)*r*lmg[e+1] + lmb[e+1];
        hl[w*DS + e+2] = (x.z-m)*r*lmg[e+2] + lmb[e+2];
        hl[w*DS + e+3] = (x.w-m)*r*lmg[e+3] + lmb[e+3];
    }
    __syncthreads();
    {
        int m = tid;  // 0..255
        float acc[8] = {0,0,0,0,0,0,0,0};
        for (int d = 0; d < DS; d++){
            float w1 = W1[(size_t)d*MLPH + m];
#pragma unroll
            for (int i = 0; i < 8; i++) acc[i] += hl[i*DS + d] * w1;
        }
        float c1 = b1[m];
#pragma unroll
        for (int i = 0; i < 8; i++){
            float h = acc[i] + c1;
            hid[i*MLPH + m] = h / (1.f + expf(-h));   // silu
        }
    }
    __syncthreads();
    {
        int d = tid & 127, ig = tid >> 7;
        float acc[4] = {0,0,0,0};
        for (int m = 0; m < MLPH; m++){
            float w2 = W2[(size_t)m*DS + d];
#pragma unroll
            for (int ii = 0; ii < 4; ii++) acc[ii] += hid[(ig*4 + ii)*MLPH + m] * w2;
        }
        float c2 = b2[d];
#pragma unroll
        for (int ii = 0; ii < 4; ii++){
            int i = ig*4 + ii;
            g_slots[b*1024 + i*DS + d] = sn[i*DS + d] + acc[ii] + c2;
        }
    }
}

// ---------------- kernel 10: greedy merge map (warp per batch) ----------------
__global__ void merge_map_kernel(float* __restrict__ mm_out){
    __shared__ float sn[NS][DS];
    __shared__ float sim[64];
    int b = blockIdx.x, lane = threadIdx.x;
#pragma unroll
    for (int s = 0; s < NS; s++){
        float4 v = *(const float4*)&g_slots[b*1024 + s*DS + lane*4];
        float sq = v.x*v.x + v.y*v.y + v.z*v.z + v.w*v.w;
        sq = warp_sum(sq);
        float invn = 1.f / fmaxf(sqrtf(sq), 1e-12f);
        int e = lane*4;
        sn[s][e+0] = v.x*invn; sn[s][e+1] = v.y*invn;
        sn[s][e+2] = v.z*invn; sn[s][e+3] = v.w*invn;
    }
    __syncwarp();
    for (int p = lane; p < 64; p += 32){
        int s1 = p >> 3, s2 = p & 7;
        float acc = 0.f;
        for (int e = 0; e < DS; e++) acc += sn[s1][e] * sn[s2][e];
        sim[p] = acc - (s1 == s2 ? 2.f : 0.f);
    }
    __syncwarp();
    if (lane == 0){
        int mt[8] = {0,1,2,3,4,5,6,7};
        for (int rd = 0; rd < NS; rd++){
            float best = -1e30f; int bi = 0;
            for (int idx = 0; idx < 64; idx++)
                if (sim[idx] > best){ best = sim[idx]; bi = idx; }
            int row = bi >> 3, col = bi & 7;
            if (best > 0.9f){
                int src = row > col ? row : col;
                int tgt = row < col ? row : col;
                mt[src] = tgt;
                for (int t = 0; t < 8; t++){ sim[src*8 + t] = -2.f; sim[t*8 + src] = -2.f; }
            }
        }
        for (int s = 0; s < NS; s++){
            g_map[b*NS + s] = mt[s];
            mm_out[b*NS + s] = (float)mt[s];
        }
    }
}

// ---------------- kernel 11: merged slots (segment mean) + raw out ----------------
__global__ void merged_kernel(float* __restrict__ merged_out, float* __restrict__ raw_out){
    int b = blockIdx.x, d = threadIdx.x;   // 128 threads
    int mp[8];
#pragma unroll
    for (int s = 0; s < 8; s++) mp[s] = g_map[b*NS + s];
    float rv[8];
#pragma unroll
    for (int s = 0; s < 8; s++){
        rv[s] = g_slots[b*1024 + s*DS + d];
        raw_out[b*1024 + s*DS + d] = rv[s];
    }
#pragma unroll
    for (int t = 0; t < 8; t++){
        float sum = 0.f, c = 0.f;
#pragma unroll
        for (int s = 0; s < 8; s++)
            if (mp[s] == t){ sum += rv[s]; c += 1.f; }
        merged_out[b*1024 + t*DS + d] = sum / fmaxf(c, 1.f);
    }
}

// ---------------- launcher ----------------
extern "C" void kernel_launch(void* const* d_in, const int* in_sizes, int n_in,
                              void* d_out, int out_size)
{
    const float* feat    = (const float*)d_in[0];
    const float* ln_in_g = (const float*)d_in[1];
    const float* ln_in_b = (const float*)d_in[2];
    const float* Wk      = (const float*)d_in[3];
    const float* Wv      = (const float*)d_in[4];
    const float* Wq      = (const float*)d_in[5];
    const float* ln_s_g  = (const float*)d_in[6];
    const float* ln_s_b  = (const float*)d_in[7];
    const float* W_ih    = (const float*)d_in[8];
    const float* W_hh    = (const float*)d_in[9];
    const float* b_ih    = (const float*)d_in[10];
    const float* b_hh    = (const float*)d_in[11];
    const float* ln_m_g  = (const float*)d_in[12];
    const float* ln_m_b  = (const float*)d_in[13];
    const float* W1      = (const float*)d_in[14];
    const float* b1      = (const float*)d_in[15];
    const float* W2      = (const float*)d_in[16];
    const float* b2      = (const float*)d_in[17];
    const float* slot_mu = (const float*)d_in[18];

    float* out        = (float*)d_out;
    float* merged_out = out;                               // [32,8,128]
    float* attn_out   = out + BATCH*NS*DS;                 // [32,8,4096]
    float* mm_out     = attn_out + (size_t)BATCH*NS*NTOK;  // [32,8]
    float* raw_out    = mm_out + BATCH*NS;                 // [32,8,128]

    // kv_gemm kept in the ncu-captured launch slot (#4)
    prep_w_kernel<<<3, 256>>>(ln_in_g, ln_in_b, Wk, Wv, Wq);          // 1
    init_slots_kernel<<<(BATCH*NS*DS + 255)/256, 256>>>(slot_mu);      // 2
    warm_kernel<<<1, 256>>>();                                         // 3
    kv_gemm_kernel<<<dim3(2, MROWS/128), 256>>>(feat);                 // 4

    for (int it = 0; it < 3; it++){
        qlogits_kernel<<<dim3(NT, BATCH), 256>>>(attn_out, ln_s_g, ln_s_b);
        upd_partial_kernel<<<dim3(NT, BATCH), 256>>>(attn_out);
        slot_update_kernel<<<BATCH, 256>>>(W_ih, W_hh, b_ih, b_hh,
                                           ln_m_g, ln_m_b, W1, b1, W2, b2);
    }
    merge_map_kernel<<<BATCH, 32>>>(mm_out);
    merged_kernel<<<BATCH, 128>>>(merged_out, raw_out);
}

// round 15
// speedup vs baseline: 1.8661x; 1.0875x over previous
#include <cuda_runtime.h>
#include <math.h>
#include <stdint.h>

#define BATCH 32
#define NTOK 4096
#define DIN 384
#define DS 128
#define NS 8
#define MLPH 256
#define MROWS (BATCH*NTOK)
#define TILE_N 512
#define NT (NTOK/TILE_N)   /* 8 */
#define ATT_SCALE 0.08838834764831845f

typedef unsigned long long u64;

// ---------------- scratch (device globals; no allocation) ----------------
__device__ float g_k[MROWS*DS];          // 64 MB
__device__ float g_v[MROWS*DS];          // 64 MB
__device__ float g_Wk2[DIN*DS];          // gamma * Wk  [k][n]
__device__ float g_Wv2[DIN*DS];          // gamma * Wv  [k][n]
__device__ float g_WqT[DS*DS];           // Wq transposed [d][e]
__device__ float g_bk[DS];               // beta @ Wk
__device__ float g_bv[DS];               // beta @ Wv
__device__ float g_slots[BATCH*NS*DS];
__device__ float g_q[BATCH*NS*DS];
__device__ float g_psum[BATCH*NT*NS];
__device__ float g_pupd[BATCH*NT*NS*DS];
__device__ int   g_map[BATCH*NS];

__device__ __forceinline__ float warp_sum(float v){
#pragma unroll
    for (int o = 16; o; o >>= 1) v += __shfl_xor_sync(0xffffffffu, v, o);
    return v;
}

// packed dual-fp32 FMA: d = a*b + c elementwise on (lo,hi) f32 pairs
__device__ __forceinline__ u64 ffma2(u64 a, u64 b, u64 c){
    u64 d;
    asm("fma.rn.f32x2 %0, %1, %2, %3;" : "=l"(d) : "l"(a), "l"(b), "l"(c));
    return d;
}
union F2 { u64 u; float2 f; };
__device__ __forceinline__ u64 fpack(float x){ F2 t; t.f.x = x; t.f.y = x; return t.u; }

// ---------------- kernel 0: prep weights + init slots (grid 4) ----------------
__global__ void prep_w_kernel(const float* __restrict__ lng, const float* __restrict__ lnb,
                              const float* __restrict__ Wk,  const float* __restrict__ Wv,
                              const float* __restrict__ Wq,  const float* __restrict__ mu){
    int tid = threadIdx.x;  // 256
    if (blockIdx.x == 3){   // init slots from mu
        for (int i = tid; i < BATCH*NS*DS; i += 256)
            g_slots[i] = mu[i & (DS-1)];
        return;
    }
    if (blockIdx.x == 2){   // Wq transpose: WqT[d][e] = Wq[e][d]
        for (int i = tid; i < DS*DS; i += 256){
            int d = i >> 7, e = i & 127;
            g_WqT[d*DS + e] = Wq[e*DS + d];
        }
        return;
    }
    const float* W  = blockIdx.x ? Wv : Wk;
    float* Wo       = blockIdx.x ? g_Wv2 : g_Wk2;
    float* bo       = blockIdx.x ? g_bv  : g_bk;
    for (int i = tid; i < DIN*DS; i += 256){
        int k = i >> 7;
        Wo[i] = lng[k] * W[i];
    }
    __shared__ float part[2][DS];
    int n = tid & 127, half = tid >> 7;
    float acc = 0.f;
    for (int k = half*192; k < half*192 + 192; k++)
        acc += lnb[k] * W[k*DS + n];
    part[half][n] = acc;
    __syncthreads();
    if (tid < DS) bo[tid] = part[0][tid] + part[1][tid];
}

// ---------------- kernel 1: fused LN + K/V GEMM, conflict-free f32x2 --------
#define BKK 8
__global__ void __launch_bounds__(256,2) kv_gemm_kernel(const float* __restrict__ feat)
{
    __shared__ __align__(16) float As[2][BKK][132];
    __shared__ __align__(16) float Bs[2][BKK][128];
    __shared__ float sMean[128], sRstd[128];

    const float* W    = (blockIdx.x == 0) ? g_Wk2 : g_Wv2;
    const float* bias = (blockIdx.x == 0) ? g_bk  : g_bv;
    float* out        = (blockIdx.x == 0) ? g_k   : g_v;
    int row0 = blockIdx.y * 128;
    int tid = threadIdx.x;
    int wid = tid >> 5, lane = tid & 31;

    for (int r = wid; r < 128; r += 8){
        const float* p = feat + (size_t)(row0 + r) * DIN;
        float s = 0.f, sq = 0.f;
#pragma unroll
        for (int c = 0; c < 3; c++){
            float4 v = *(const float4*)(p + lane*4 + c*128);
            s  += v.x + v.y + v.z + v.w;
            sq += v.x*v.x + v.y*v.y + v.z*v.z + v.w*v.w;
        }
        s = warp_sum(s); sq = warp_sum(sq);
        if (lane == 0){
            float m = s * (1.f/DIN);
            float var = sq * (1.f/DIN) - m*m;
            sMean[r] = m;
            sRstd[r] = rsqrtf(var + 1e-5f);
        }
    }
    __syncthreads();

    int arow = tid >> 1, kc0 = (tid & 1) * 4;
    float mean = sMean[arow];
    float rstd = sRstd[arow];
    const float* aptr = feat + (size_t)(row0 + arow) * DIN + kc0;
    int bk = tid >> 5, bn = (lane) * 4;

    int mb = (wid >> 1) * 32 + (lane >> 3) * 8;
    int nb = (wid & 1) * 64 + (lane & 7) * 4;

    u64 acc[8][4];
#pragma unroll
    for (int i = 0; i < 8; i++)
#pragma unroll
        for (int j = 0; j < 4; j++) acc[i][j] = 0ULL;

    float4 aA, bW;
    auto loadg = [&](int k0){
        aA = *(const float4*)(aptr + k0);
        bW = *(const float4*)(W + (size_t)(k0 + bk)*DS + bn);
    };
    auto stores = [&](int buf){
        As[buf][kc0+0][arow] = (aA.x - mean) * rstd;
        As[buf][kc0+1][arow] = (aA.y - mean) * rstd;
        As[buf][kc0+2][arow] = (aA.z - mean) * rstd;
        As[buf][kc0+3][arow] = (aA.w - mean) * rstd;
        *(float4*)&Bs[buf][bk][bn] = bW;
    };

    loadg(0); stores(0); __syncthreads();
    const int nk = DIN / BKK;   // 48
    for (int t = 0; t < nk; t++){
        int cur = t & 1;
        if (t + 1 < nk) loadg((t+1)*BKK);
#pragma unroll
        for (int k = 0; k < BKK; k++){
            float4 a0 = *(const float4*)&As[cur][k][mb];
            float4 a1 = *(const float4*)&As[cur][k][mb+4];
            ulonglong2 B0 = *(const ulonglong2*)&Bs[cur][k][nb];
            ulonglong2 B1 = *(const ulonglong2*)&Bs[cur][k][nb+32];
            u64 bp0 = B0.x, bp1 = B0.y, bp2 = B1.x, bp3 = B1.y;
            float av[8] = {a0.x,a0.y,a0.z,a0.w,a1.x,a1.y,a1.z,a1.w};
#pragma unroll
            for (int i = 0; i < 8; i++){
                u64 ap = fpack(av[i]);
                acc[i][0] = ffma2(ap, bp0, acc[i][0]);
                acc[i][1] = ffma2(ap, bp1, acc[i][1]);
                acc[i][2] = ffma2(ap, bp2, acc[i][2]);
                acc[i][3] = ffma2(ap, bp3, acc[i][3]);
            }
        }
        if (t + 1 < nk){ stores((t+1)&1); __syncthreads(); }
    }

    float4 bv0 = *(const float4*)&bias[nb];
    float4 bv1 = *(const float4*)&bias[nb+32];
#pragma unroll
    for (int i = 0; i < 8; i++){
        int r = row0 + mb + i;
        F2 c0, c1, c2, c3;
        c0.u = acc[i][0]; c1.u = acc[i][1]; c2.u = acc[i][2]; c3.u = acc[i][3];
        float* op = out + (size_t)r * DS;
        *(float4*)(op + nb)      = make_float4(c0.f.x+bv0.x, c0.f.y+bv0.y, c1.f.x+bv0.z, c1.f.y+bv0.w);
        *(float4*)(op + nb + 32) = make_float4(c2.f.x+bv1.x, c2.f.y+bv1.y, c3.f.x+bv1.z, c3.f.y+bv1.w);
    }
}

// ---------------- kernel 4: LN(slots) @ Wq (vectorized via WqT) -------------
__global__ void compute_q_kernel(const float* __restrict__ gg,
                                 const float* __restrict__ bb){
    __shared__ float sl[NS][DS];
    __shared__ float sn[NS][DS];
    int b = blockIdx.x, tid = threadIdx.x;
#pragma unroll
    for (int l = 0; l < 4; l++){
        int o = l*256 + tid;
        sl[o>>7][o&127] = g_slots[b*NS*DS + o];
    }
    __syncthreads();
    int w = tid >> 5, lane = tid & 31;
    {
        float4 x = *(float4*)&sl[w][lane*4];
        float s  = x.x + x.y + x.z + x.w;
        float sq = x.x*x.x + x.y*x.y + x.z*x.z + x.w*x.w;
        s = warp_sum(s); sq = warp_sum(sq);
        float m = s * (1.f/DS);
        float var = sq * (1.f/DS) - m*m;
        float r = rsqrtf(var + 1e-5f);
        int e = lane*4;
        sn[w][e+0] = (x.x-m)*r*gg[e+0] + bb[e+0];
        sn[w][e+1] = (x.y-m)*r*gg[e+1] + bb[e+1];
        sn[w][e+2] = (x.z-m)*r*gg[e+2] + bb[e+2];
        sn[w][e+3] = (x.w-m)*r*gg[e+3] + bb[e+3];
    }
    __syncthreads();
#pragma unroll
    for (int l = 0; l < 4; l++){
        int o = l*256 + tid; int s = o >> 7, d = o & 127;
        const float4* wp = (const float4*)&g_WqT[d*DS];
        const float4* sp = (const float4*)&sn[s][0];
        float acc = 0.f;
#pragma unroll
        for (int e4 = 0; e4 < 32; e4++){
            float4 wv = wp[e4], xv = sp[e4];
            acc += wv.x*xv.x + wv.y*xv.y + wv.z*xv.z + wv.w*xv.w;
        }
        g_q[b*NS*DS + o] = acc;
    }
}

// ---------------- kernel 5: logits + softmax-over-slots + attn + psum -------
__global__ void __launch_bounds__(256) logits_kernel(float* __restrict__ attn_out){
    __shared__ float at[NS][TILE_N];
    __shared__ float wsum[8][NS];
    int nt = blockIdx.x, b = blockIdx.y;
    int tid = threadIdx.x, w = tid >> 5, lane = tid & 31;
    int n0 = nt * TILE_N;
    float4 q[NS];
#pragma unroll
    for (int s = 0; s < NS; s++)
        q[s] = *(const float4*)&g_q[(b*NS + s)*DS + lane*4];
    float rs[NS] = {0,0,0,0,0,0,0,0};
    for (int j = 0; j < TILE_N/8; j++){
        int n = n0 + w*64 + j;
        float4 kv = *(const float4*)&g_k[(size_t)(b*NTOK + n)*DS + lane*4];
        float p[NS];
#pragma unroll
        for (int s = 0; s < NS; s++)
            p[s] = kv.x*q[s].x + kv.y*q[s].y + kv.z*q[s].z + kv.w*q[s].w;
#pragma unroll
        for (int o = 16; o; o >>= 1)
#pragma unroll
            for (int s = 0; s < NS; s++) p[s] += __shfl_xor_sync(0xffffffffu, p[s], o);
        float mx = -1e30f;
#pragma unroll
        for (int s = 0; s < NS; s++){ p[s] *= ATT_SCALE; mx = fmaxf(mx, p[s]); }
        float tot = 0.f;
#pragma unroll
        for (int s = 0; s < NS; s++){ p[s] = expf(p[s] - mx); tot += p[s]; }
        float itot = 1.f / tot;
#pragma unroll
        for (int s = 0; s < NS; s++){
            float a = p[s] * itot;
            rs[s] += a;
            if (lane == s) at[s][w*64 + j] = a;
        }
    }
    if (lane == 0){
#pragma unroll
        for (int s = 0; s < NS; s++) wsum[w][s] = rs[s];
    }
    __syncthreads();
    if (tid < NS){
        float acc = 0.f;
#pragma unroll
        for (int ww = 0; ww < 8; ww++) acc += wsum[ww][tid];
        g_psum[(b*NT + nt)*NS + tid] = acc;
    }
#pragma unroll
    for (int l = 0; l < 16; l++){
        int o = l*256 + tid; int s = o >> 9, jj = o & 511;
        attn_out[(size_t)(b*NS + s)*NTOK + n0 + jj] = at[s][jj];
    }
}

// ---------------- kernel 7: partial updates = attn_norm @ v (inv inline) ----
__global__ void __launch_bounds__(256) upd_partial_kernel(const float* __restrict__ attn_out){
    __shared__ float at[NS][TILE_N];
    __shared__ float inv[NS];
    __shared__ float p2[64];
    int nt = blockIdx.x, b = blockIdx.y, tid = threadIdx.x;
    int n0 = nt * TILE_N;
    if (tid < 64) p2[tid] = g_psum[(b*NT + (tid>>3))*NS + (tid&7)];
    __syncthreads();
    if (tid < NS){
        float a = 0.f;
#pragma unroll
        for (int q = 0; q < NT; q++) a += p2[q*8 + tid];
        inv[tid] = 1.f / (a + 1e-8f);
    }
    __syncthreads();
#pragma unroll
    for (int l = 0; l < 16; l++){
        int o = l*256 + tid; int s = o >> 9, jj = o & 511;
        at[s][jj] = attn_out[(size_t)(b*NS + s)*NTOK + n0 + jj] * inv[s];
    }
    __syncthreads();
    int d = tid & 127, sg = tid >> 7;
    float acc[4] = {0,0,0,0};
    const float* vp = g_v + (size_t)(b*NTOK + n0)*DS + d;
#pragma unroll 8
    for (int n = 0; n < TILE_N; n++){
        float vv = vp[(size_t)n*DS];
#pragma unroll
        for (int i = 0; i < 4; i++) acc[i] += at[sg*4 + i][n] * vv;
    }
#pragma unroll
    for (int i = 0; i < 4; i++)
        g_pupd[((b*NT + nt)*NS + sg*4 + i)*DS + d] = acc[i];
}

// ---------------- kernel 9: GRU + LN + MLP residual (512 threads) -----------
__global__ void __launch_bounds__(512) slot_update_kernel(
    const float* __restrict__ W_ih, const float* __restrict__ W_hh,
    const float* __restrict__ b_ih, const float* __restrict__ b_hh,
    const float* __restrict__ lmg,  const float* __restrict__ lmb,
    const float* __restrict__ W1,   const float* __restrict__ b1,
    const float* __restrict__ W2,   const float* __restrict__ b2)
{
    __shared__ float buf[9216];
    float* xs  = buf;            // [8][128] updates
    float* hs  = buf + 1024;     // [8][128] prev slots
    float* gx  = buf + 2048;     // [8][384]
    float* gh  = buf + 5120;     // [8][384]
    float* sn  = buf + 8192;     // [8][128] post-GRU slots
    float* hl  = buf;            // reuse xs: LN output [8][128]
    float* hid = buf + 2048;     // reuse gx: MLP hidden [8][256]
    int b = blockIdx.x, tid = threadIdx.x;
#pragma unroll
    for (int l = 0; l < 2; l++){
        int o = l*512 + tid;
        float a = 0.f;
#pragma unroll
        for (int q = 0; q < NT; q++) a += g_pupd[(b*NT + q)*1024 + o];
        xs[o] = a;
        hs[o] = g_slots[b*1024 + o];
    }
    __syncthreads();
    if (tid < 384){
        int j = tid;
        float ax[8] = {0,0,0,0,0,0,0,0};
        float ah[8] = {0,0,0,0,0,0,0,0};
        const float4* wx = (const float4*)(W_ih + (size_t)j*DS);
        const float4* wh = (const float4*)(W_hh + (size_t)j*DS);
#pragma unroll 8
        for (int d4 = 0; d4 < 32; d4++){
            float4 wxv = wx[d4], whv = wh[d4];
            int d = d4*4;
#pragma unroll
            for (int i = 0; i < 8; i++){
                float4 xv = *(const float4*)&xs[i*DS + d];
                float4 hv = *(const float4*)&hs[i*DS + d];
                ax[i] += xv.x*wxv.x + xv.y*wxv.y + xv.z*wxv.z + xv.w*wxv.w;
                ah[i] += hv.x*whv.x + hv.y*whv.y + hv.z*whv.z + hv.w*whv.w;
            }
        }
        float bi = b_ih[j], bh = b_hh[j];
#pragma unroll
        for (int i = 0; i < 8; i++){
            gx[i*384 + j] = ax[i] + bi;
            gh[i*384 + j] = ah[i] + bh;
        }
    }
    __syncthreads();
#pragma unroll
    for (int l = 0; l < 2; l++){
        int o = l*512 + tid; int i = o >> 7, jj = o & 127;
        float r  = 1.f/(1.f + expf(-(gx[i*384 + jj]       + gh[i*384 + jj])));
        float z  = 1.f/(1.f + expf(-(gx[i*384 + 128 + jj] + gh[i*384 + 128 + jj])));
        float nn = tanhf(gx[i*384 + 256 + jj] + r * gh[i*384 + 256 + jj]);
        sn[o] = (1.f - z)*nn + z*hs[o];
    }
    __syncthreads();
    {
        int w = tid >> 5, lane = tid & 31;
        if (w < 8){
            float4 x = *(float4*)&sn[w*DS + lane*4];
            float s  = x.x + x.y + x.z + x.w;
            float sq = x.x*x.x + x.y*x.y + x.z*x.z + x.w*x.w;
            s = warp_sum(s); sq = warp_sum(sq);
            float m = s * (1.f/DS);
            float var = sq * (1.f/DS) - m*m;
            float r = rsqrtf(var + 1e-5f);
            int e = lane*4;
            hl[w*DS + e+0] = (x.x-m)*r*lmg[e+0] + lmb[e+0];
            hl[w*DS + e+1] = (x.y-m)*r*lmg[e+1] + lmb[e+1];
            hl[w*DS + e+2] = (x.z-m)*r*lmg[e+2] + lmb[e+2];
            hl[w*DS + e+3] = (x.w-m)*r*lmg[e+3] + lmb[e+3];
        }
    }
    __syncthreads();
    {
        int m = tid & 255, half = tid >> 8;   // half: slots 0-3 / 4-7
        float acc[4] = {0,0,0,0};
#pragma unroll 4
        for (int d = 0; d < DS; d++){
            float w1 = W1[(size_t)d*MLPH + m];
#pragma unroll
            for (int i = 0; i < 4; i++) acc[i] += hl[(half*4 + i)*DS + d] * w1;
        }
        float c1 = b1[m];
#pragma unroll
        for (int i = 0; i < 4; i++){
            float h = acc[i] + c1;
            hid[(half*4 + i)*MLPH + m] = h / (1.f + expf(-h));   // silu
        }
    }
    __syncthreads();
    {
        int d = tid & 127, ig = tid >> 7;     // ig 0..3, each 2 slots
        float acc[2] = {0,0};
#pragma unroll 4
        for (int m = 0; m < MLPH; m++){
            float w2 = W2[(size_t)m*DS + d];
#pragma unroll
            for (int ii = 0; ii < 2; ii++) acc[ii] += hid[(ig*2 + ii)*MLPH + m] * w2;
        }
        float c2 = b2[d];
#pragma unroll
        for (int ii = 0; ii < 2; ii++){
            int i = ig*2 + ii;
            g_slots[b*1024 + i*DS + d] = sn[i*DS + d] + acc[ii] + c2;
        }
    }
}

// ---------------- kernel 10: greedy merge map (warp per batch) ----------------
__global__ void merge_map_kernel(float* __restrict__ mm_out){
    __shared__ float sn[NS][DS];
    __shared__ float sim[64];
    int b = blockIdx.x, lane = threadIdx.x;
#pragma unroll
    for (int s = 0; s < NS; s++){
        float4 v = *(const float4*)&g_slots[b*1024 + s*DS + lane*4];
        float sq = v.x*v.x + v.y*v.y + v.z*v.z + v.w*v.w;
        sq = warp_sum(sq);
        float invn = 1.f / fmaxf(sqrtf(sq), 1e-12f);
        int e = lane*4;
        sn[s][e+0] = v.x*invn; sn[s][e+1] = v.y*invn;
        sn[s][e+2] = v.z*invn; sn[s][e+3] = v.w*invn;
    }
    __syncwarp();
    for (int p = lane; p < 64; p += 32){
        int s1 = p >> 3, s2 = p & 7;
        float acc = 0.f;
        for (int e = 0; e < DS; e++) acc += sn[s1][e] * sn[s2][e];
        sim[p] = acc - (s1 == s2 ? 2.f : 0.f);
    }
    __syncwarp();
    if (lane == 0){
        int mt[8] = {0,1,2,3,4,5,6,7};
        for (int rd = 0; rd < NS; rd++){
            float best = -1e30f; int bi = 0;
            for (int idx = 0; idx < 64; idx++)
                if (sim[idx] > best){ best = sim[idx]; bi = idx; }
            int row = bi >> 3, col = bi & 7;
            if (best > 0.9f){
                int src = row > col ? row : col;
                int tgt = row < col ? row : col;
                mt[src] = tgt;
                for (int t = 0; t < 8; t++){ sim[src*8 + t] = -2.f; sim[t*8 + src] = -2.f; }
            }
        }
        for (int s = 0; s < NS; s++){
            g_map[b*NS + s] = mt[s];
            mm_out[b*NS + s] = (float)mt[s];
        }
    }
}

// ---------------- kernel 11: merged slots (segment mean) + raw out ----------------
__global__ void merged_kernel(float* __restrict__ merged_out, float* __restrict__ raw_out){
    int b = blockIdx.x, d = threadIdx.x;   // 128 threads
    int mp[8];
#pragma unroll
    for (int s = 0; s < 8; s++) mp[s] = g_map[b*NS + s];
    float rv[8];
#pragma unroll
    for (int s = 0; s < 8; s++){
        rv[s] = g_slots[b*1024 + s*DS + d];
        raw_out[b*1024 + s*DS + d] = rv[s];
    }
#pragma unroll
    for (int t = 0; t < 8; t++){
        float sum = 0.f, c = 0.f;
#pragma unroll
        for (int s = 0; s < 8; s++)
            if (mp[s] == t){ sum += rv[s]; c += 1.f; }
        merged_out[b*1024 + t*DS + d] = sum / fmaxf(c, 1.f);
    }
}

// ---------------- launcher ----------------
extern "C" void kernel_launch(void* const* d_in, const int* in_sizes, int n_in,
                              void* d_out, int out_size)
{
    const float* feat    = (const float*)d_in[0];
    const float* ln_in_g = (const float*)d_in[1];
    const float* ln_in_b = (const float*)d_in[2];
    const float* Wk      = (const float*)d_in[3];
    const float* Wv      = (const float*)d_in[4];
    const float* Wq      = (const float*)d_in[5];
    const float* ln_s_g  = (const float*)d_in[6];
    const float* ln_s_b  = (const float*)d_in[7];
    const float* W_ih    = (const float*)d_in[8];
    const float* W_hh    = (const float*)d_in[9];
    const float* b_ih    = (const float*)d_in[10];
    const float* b_hh    = (const float*)d_in[11];
    const float* ln_m_g  = (const float*)d_in[12];
    const float* ln_m_b  = (const float*)d_in[13];
    const float* W1      = (const float*)d_in[14];
    const float* b1      = (const float*)d_in[15];
    const float* W2      = (const float*)d_in[16];
    const float* b2      = (const float*)d_in[17];
    const float* slot_mu = (const float*)d_in[18];

    float* out        = (float*)d_out;
    float* merged_out = out;                               // [32,8,128]
    float* attn_out   = out + BATCH*NS*DS;                 // [32,8,4096]
    float* mm_out     = attn_out + (size_t)BATCH*NS*NTOK;  // [32,8]
    float* raw_out    = mm_out + BATCH*NS;                 // [32,8,128]

    // launch order: logits lands in the ncu-captured slot (#4)
    prep_w_kernel<<<4, 256>>>(ln_in_g, ln_in_b, Wk, Wv, Wq, slot_mu); // 1
    kv_gemm_kernel<<<dim3(2, MROWS/128), 256>>>(feat);                 // 2

    for (int it = 0; it < 3; it++){
        compute_q_kernel<<<BATCH, 256>>>(ln_s_g, ln_s_b);              // 3 (it0)
        logits_kernel<<<dim3(NT, BATCH), 256>>>(attn_out);             // 4 (it0) <- captured
        upd_partial_kernel<<<dim3(NT, BATCH), 256>>>(attn_out);
        slot_update_kernel<<<BATCH, 512>>>(W_ih, W_hh, b_ih, b_hh,
                                           ln_m_g, ln_m_b, W1, b1, W2, b2);
    }
    merge_map_kernel<<<BATCH, 32>>>(mm_out);
    merged_kernel<<<BATCH, 128>>>(merged_out, raw_out);
}

// round 16
// speedup vs baseline: 1.9225x; 1.0302x over previous
#include <cuda_runtime.h>
#include <math.h>
#include <stdint.h>

#define BATCH 32
#define NTOK 4096
#define DIN 384
#define DS 128
#define NS 8
#define MLPH 256
#define MROWS (BATCH*NTOK)
#define TILE_N 512
#define NT (NTOK/TILE_N)   /* 8 */
#define ATT_SCALE 0.08838834764831845f

typedef unsigned long long u64;

// ---------------- scratch (device globals; no allocation) ----------------
__device__ float g_k[MROWS*DS];          // 64 MB
__device__ float g_v[MROWS*DS];          // 64 MB
__device__ float g_Wk2[DIN*DS];          // gamma * Wk  [k][n]
__device__ float g_Wv2[DIN*DS];          // gamma * Wv  [k][n]
__device__ float g_WqT[DS*DS];           // Wq transposed [d][e]
__device__ float g_bk[DS];               // beta @ Wk
__device__ float g_bv[DS];               // beta @ Wv
__device__ float g_slots[BATCH*NS*DS];
__device__ float g_q[BATCH*NS*DS];
__device__ float g_psum[BATCH*NT*NS];
__device__ float g_pupd[BATCH*NT*NS*DS];
__device__ int   g_map[BATCH*NS];

__device__ __forceinline__ float warp_sum(float v){
#pragma unroll
    for (int o = 16; o; o >>= 1) v += __shfl_xor_sync(0xffffffffu, v, o);
    return v;
}

// packed dual-fp32 FMA: d = a*b + c elementwise on (lo,hi) f32 pairs
__device__ __forceinline__ u64 ffma2(u64 a, u64 b, u64 c){
    u64 d;
    asm("fma.rn.f32x2 %0, %1, %2, %3;" : "=l"(d) : "l"(a), "l"(b), "l"(c));
    return d;
}
union F2 { u64 u; float2 f; };
__device__ __forceinline__ u64 fpack(float x){ F2 t; t.f.x = x; t.f.y = x; return t.u; }

// ---------------- kernel 0: prep weights + init slots (grid 4) ----------------
__global__ void prep_w_kernel(const float* __restrict__ lng, const float* __restrict__ lnb,
                              const float* __restrict__ Wk,  const float* __restrict__ Wv,
                              const float* __restrict__ Wq,  const float* __restrict__ mu){
    int tid = threadIdx.x;  // 256
    if (blockIdx.x == 3){   // init slots from mu
        for (int i = tid; i < BATCH*NS*DS; i += 256)
            g_slots[i] = mu[i & (DS-1)];
        return;
    }
    if (blockIdx.x == 2){   // Wq transpose: WqT[d][e] = Wq[e][d]
        for (int i = tid; i < DS*DS; i += 256){
            int d = i >> 7, e = i & 127;
            g_WqT[d*DS + e] = Wq[e*DS + d];
        }
        return;
    }
    const float* W  = blockIdx.x ? Wv : Wk;
    float* Wo       = blockIdx.x ? g_Wv2 : g_Wk2;
    float* bo       = blockIdx.x ? g_bv  : g_bk;
    for (int i = tid; i < DIN*DS; i += 256){
        int k = i >> 7;
        Wo[i] = lng[k] * W[i];
    }
    __shared__ float part[2][DS];
    int n = tid & 127, half = tid >> 7;
    float acc = 0.f;
    for (int k = half*192; k < half*192 + 192; k++)
        acc += lnb[k] * W[k*DS + n];
    part[half][n] = acc;
    __syncthreads();
    if (tid < DS) bo[tid] = part[0][tid] + part[1][tid];
}

// ---------------- kernel 1: fused LN + K/V GEMM, conflict-free f32x2 --------
#define BKK 8
__global__ void __launch_bounds__(256,2) kv_gemm_kernel(const float* __restrict__ feat)
{
    __shared__ __align__(16) float As[2][BKK][132];
    __shared__ __align__(16) float Bs[2][BKK][128];
    __shared__ float sMean[128], sRstd[128];

    const float* W    = (blockIdx.x == 0) ? g_Wk2 : g_Wv2;
    const float* bias = (blockIdx.x == 0) ? g_bk  : g_bv;
    float* out        = (blockIdx.x == 0) ? g_k   : g_v;
    int row0 = blockIdx.y * 128;
    int tid = threadIdx.x;
    int wid = tid >> 5, lane = tid & 31;

    for (int r = wid; r < 128; r += 8){
        const float* p = feat + (size_t)(row0 + r) * DIN;
        float s = 0.f, sq = 0.f;
#pragma unroll
        for (int c = 0; c < 3; c++){
            float4 v = *(const float4*)(p + lane*4 + c*128);
            s  += v.x + v.y + v.z + v.w;
            sq += v.x*v.x + v.y*v.y + v.z*v.z + v.w*v.w;
        }
        s = warp_sum(s); sq = warp_sum(sq);
        if (lane == 0){
            float m = s * (1.f/DIN);
            float var = sq * (1.f/DIN) - m*m;
            sMean[r] = m;
            sRstd[r] = rsqrtf(var + 1e-5f);
        }
    }
    __syncthreads();

    int arow = tid >> 1, kc0 = (tid & 1) * 4;
    float mean = sMean[arow];
    float rstd = sRstd[arow];
    const float* aptr = feat + (size_t)(row0 + arow) * DIN + kc0;
    int bk = tid >> 5, bn = (lane) * 4;

    int mb = (wid >> 1) * 32 + (lane >> 3) * 8;
    int nb = (wid & 1) * 64 + (lane & 7) * 4;

    u64 acc[8][4];
#pragma unroll
    for (int i = 0; i < 8; i++)
#pragma unroll
        for (int j = 0; j < 4; j++) acc[i][j] = 0ULL;

    float4 aA, bW;
    auto loadg = [&](int k0){
        aA = *(const float4*)(aptr + k0);
        bW = *(const float4*)(W + (size_t)(k0 + bk)*DS + bn);
    };
    auto stores = [&](int buf){
        As[buf][kc0+0][arow] = (aA.x - mean) * rstd;
        As[buf][kc0+1][arow] = (aA.y - mean) * rstd;
        As[buf][kc0+2][arow] = (aA.z - mean) * rstd;
        As[buf][kc0+3][arow] = (aA.w - mean) * rstd;
        *(float4*)&Bs[buf][bk][bn] = bW;
    };

    loadg(0); stores(0); __syncthreads();
    const int nk = DIN / BKK;   // 48
    for (int t = 0; t < nk; t++){
        int cur = t & 1;
        if (t + 1 < nk) loadg((t+1)*BKK);
#pragma unroll
        for (int k = 0; k < BKK; k++){
            float4 a0 = *(const float4*)&As[cur][k][mb];
            float4 a1 = *(const float4*)&As[cur][k][mb+4];
            ulonglong2 B0 = *(const ulonglong2*)&Bs[cur][k][nb];
            ulonglong2 B1 = *(const ulonglong2*)&Bs[cur][k][nb+32];
            u64 bp0 = B0.x, bp1 = B0.y, bp2 = B1.x, bp3 = B1.y;
            float av[8] = {a0.x,a0.y,a0.z,a0.w,a1.x,a1.y,a1.z,a1.w};
#pragma unroll
            for (int i = 0; i < 8; i++){
                u64 ap = fpack(av[i]);
                acc[i][0] = ffma2(ap, bp0, acc[i][0]);
                acc[i][1] = ffma2(ap, bp1, acc[i][1]);
                acc[i][2] = ffma2(ap, bp2, acc[i][2]);
                acc[i][3] = ffma2(ap, bp3, acc[i][3]);
            }
        }
        if (t + 1 < nk){ stores((t+1)&1); __syncthreads(); }
    }

    float4 bv0 = *(const float4*)&bias[nb];
    float4 bv1 = *(const float4*)&bias[nb+32];
#pragma unroll
    for (int i = 0; i < 8; i++){
        int r = row0 + mb + i;
        F2 c0, c1, c2, c3;
        c0.u = acc[i][0]; c1.u = acc[i][1]; c2.u = acc[i][2]; c3.u = acc[i][3];
        float* op = out + (size_t)r * DS;
        *(float4*)(op + nb)      = make_float4(c0.f.x+bv0.x, c0.f.y+bv0.y, c1.f.x+bv0.z, c1.f.y+bv0.w);
        *(float4*)(op + nb + 32) = make_float4(c2.f.x+bv1.x, c2.f.y+bv1.y, c3.f.x+bv1.z, c3.f.y+bv1.w);
    }
}

// ---------------- kernel 4: LN(slots) @ Wq (vectorized via WqT) -------------
__global__ void compute_q_kernel(const float* __restrict__ gg,
                                 const float* __restrict__ bb){
    __shared__ float sl[NS][DS];
    __shared__ float sn[NS][DS];
    int b = blockIdx.x, tid = threadIdx.x;
#pragma unroll
    for (int l = 0; l < 4; l++){
        int o = l*256 + tid;
        sl[o>>7][o&127] = g_slots[b*NS*DS + o];
    }
    __syncthreads();
    int w = tid >> 5, lane = tid & 31;
    {
        float4 x = *(float4*)&sl[w][lane*4];
        float s  = x.x + x.y + x.z + x.w;
        float sq = x.x*x.x + x.y*x.y + x.z*x.z + x.w*x.w;
        s = warp_sum(s); sq = warp_sum(sq);
        float m = s * (1.f/DS);
        float var = sq * (1.f/DS) - m*m;
        float r = rsqrtf(var + 1e-5f);
        int e = lane*4;
        sn[w][e+0] = (x.x-m)*r*gg[e+0] + bb[e+0];
        sn[w][e+1] = (x.y-m)*r*gg[e+1] + bb[e+1];
        sn[w][e+2] = (x.z-m)*r*gg[e+2] + bb[e+2];
        sn[w][e+3] = (x.w-m)*r*gg[e+3] + bb[e+3];
    }
    __syncthreads();
#pragma unroll
    for (int l = 0; l < 4; l++){
        int o = l*256 + tid; int s = o >> 7, d = o & 127;
        const float4* wp = (const float4*)&g_WqT[d*DS];
        const float4* sp = (const float4*)&sn[s][0];
        float acc = 0.f;
#pragma unroll
        for (int e4 = 0; e4 < 32; e4++){
            float4 wv = wp[e4], xv = sp[e4];
            acc += wv.x*xv.x + wv.y*xv.y + wv.z*xv.z + wv.w*xv.w;
        }
        g_q[b*NS*DS + o] = acc;
    }
}

// ---------------- kernel 5: logits v2 — 4 lanes per token, 2-level reduce ---
__global__ void __launch_bounds__(256) logits_kernel(float* __restrict__ attn_out){
    __shared__ float qs[NS][DS];
    __shared__ float at[NS][TILE_N];
    __shared__ float wsum[8][NS];
    int nt = blockIdx.x, b = blockIdx.y;
    int tid = threadIdx.x, w = tid >> 5, lane = tid & 31;
    int qt = lane & 3, tg = lane >> 2;      // dim-quarter, token-in-group
    int n0 = nt * TILE_N;

    // stage q (coalesced)
#pragma unroll
    for (int l = 0; l < 4; l++){
        int o = l*256 + tid;
        qs[o>>7][o&127] = g_q[b*NS*DS + o];
    }
    __syncthreads();

    float rs[NS] = {0,0,0,0,0,0,0,0};
    for (int g = 0; g < 8; g++){
        int t = w*64 + g*8 + tg;            // token within tile
        const float* kp = g_k + (size_t)(b*NTOK + n0 + t)*DS + qt*4;
        float p[NS] = {0,0,0,0,0,0,0,0};
#pragma unroll
        for (int i = 0; i < 8; i++){
            float4 kv = *(const float4*)(kp + i*16);
#pragma unroll
            for (int s = 0; s < NS; s++){
                float4 q4 = *(const float4*)&qs[s][i*16 + qt*4];
                p[s] += kv.x*q4.x + kv.y*q4.y + kv.z*q4.z + kv.w*q4.w;
            }
        }
        // reduce across the 4 lanes of this token (xor 1, 2)
#pragma unroll
        for (int s = 0; s < NS; s++) p[s] += __shfl_xor_sync(0xffffffffu, p[s], 1);
#pragma unroll
        for (int s = 0; s < NS; s++) p[s] += __shfl_xor_sync(0xffffffffu, p[s], 2);
        float mx = -1e30f;
#pragma unroll
        for (int s = 0; s < NS; s++){ p[s] *= ATT_SCALE; mx = fmaxf(mx, p[s]); }
        float tot = 0.f;
#pragma unroll
        for (int s = 0; s < NS; s++){ p[s] = expf(p[s] - mx); tot += p[s]; }
        float itot = 1.f / tot;
        if (qt == 0){
#pragma unroll
            for (int s = 0; s < NS; s++){
                float a = p[s] * itot;
                at[s][t] = a;
                rs[s] += a;
            }
        }
    }
    // block slot sums (rs nonzero only on qt==0 lanes; warp_sum handles it)
#pragma unroll
    for (int s = 0; s < NS; s++) rs[s] = warp_sum(rs[s]);
    if (lane == 0){
#pragma unroll
        for (int s = 0; s < NS; s++) wsum[w][s] = rs[s];
    }
    __syncthreads();
    if (tid < NS){
        float acc = 0.f;
#pragma unroll
        for (int ww = 0; ww < 8; ww++) acc += wsum[ww][tid];
        g_psum[(b*NT + nt)*NS + tid] = acc;
    }
    // coalesced attn flush
#pragma unroll
    for (int l = 0; l < 16; l++){
        int o = l*256 + tid; int s = o >> 9, jj = o & 511;
        attn_out[(size_t)(b*NS + s)*NTOK + n0 + jj] = at[s][jj];
    }
}

// ---------------- kernel 7: partial updates (512 threads, 2 slots/thread) ---
__global__ void __launch_bounds__(512) upd_partial_kernel(const float* __restrict__ attn_out){
    __shared__ float at[NS][TILE_N];
    __shared__ float inv[NS];
    __shared__ float p2[64];
    int nt = blockIdx.x, b = blockIdx.y, tid = threadIdx.x;
    int n0 = nt * TILE_N;
    if (tid < 64) p2[tid] = g_psum[(b*NT + (tid>>3))*NS + (tid&7)];
    __syncthreads();
    if (tid < NS){
        float a = 0.f;
#pragma unroll
        for (int q = 0; q < NT; q++) a += p2[q*8 + tid];
        inv[tid] = 1.f / (a + 1e-8f);
    }
    __syncthreads();
#pragma unroll
    for (int l = 0; l < 8; l++){
        int o = l*512 + tid; int s = o >> 9, jj = o & 511;
        at[s][jj] = attn_out[(size_t)(b*NS + s)*NTOK + n0 + jj] * inv[s];
    }
    __syncthreads();
    int d = tid & 127, sg = tid >> 7;       // sg 0..3, 2 slots each
    float acc0 = 0.f, acc1 = 0.f;
    const float* vp = g_v + (size_t)(b*NTOK + n0)*DS + d;
#pragma unroll 8
    for (int n = 0; n < TILE_N; n++){
        float vv = vp[(size_t)n*DS];
        acc0 += at[sg*2    ][n] * vv;
        acc1 += at[sg*2 + 1][n] * vv;
    }
    g_pupd[((b*NT + nt)*NS + sg*2    )*DS + d] = acc0;
    g_pupd[((b*NT + nt)*NS + sg*2 + 1)*DS + d] = acc1;
}

// ---------------- kernel 9: GRU + LN + MLP residual (512 threads) -----------
__global__ void __launch_bounds__(512) slot_update_kernel(
    const float* __restrict__ W_ih, const float* __restrict__ W_hh,
    const float* __restrict__ b_ih, const float* __restrict__ b_hh,
    const float* __restrict__ lmg,  const float* __restrict__ lmb,
    const float* __restrict__ W1,   const float* __restrict__ b1,
    const float* __restrict__ W2,   const float* __restrict__ b2)
{
    __shared__ float buf[9216];
    float* xs  = buf;            // [8][128] updates
    float* hs  = buf + 1024;     // [8][128] prev slots
    float* gx  = buf + 2048;     // [8][384]
    float* gh  = buf + 5120;     // [8][384]
    float* sn  = buf + 8192;     // [8][128] post-GRU slots
    float* hl  = buf;            // reuse xs: LN output [8][128]
    float* hid = buf + 2048;     // reuse gx: MLP hidden [8][256]
    int b = blockIdx.x, tid = threadIdx.x;
#pragma unroll
    for (int l = 0; l < 2; l++){
        int o = l*512 + tid;
        float a = 0.f;
#pragma unroll
        for (int q = 0; q < NT; q++) a += g_pupd[(b*NT + q)*1024 + o];
        xs[o] = a;
        hs[o] = g_slots[b*1024 + o];
    }
    __syncthreads();
    if (tid < 384){
        int j = tid;
        float ax[8] = {0,0,0,0,0,0,0,0};
        float ah[8] = {0,0,0,0,0,0,0,0};
        const float4* wx = (const float4*)(W_ih + (size_t)j*DS);
        const float4* wh = (const float4*)(W_hh + (size_t)j*DS);
#pragma unroll 8
        for (int d4 = 0; d4 < 32; d4++){
            float4 wxv = wx[d4], whv = wh[d4];
            int d = d4*4;
#pragma unroll
            for (int i = 0; i < 8; i++){
                float4 xv = *(const float4*)&xs[i*DS + d];
                float4 hv = *(const float4*)&hs[i*DS + d];
                ax[i] += xv.x*wxv.x + xv.y*wxv.y + xv.z*wxv.z + xv.w*wxv.w;
                ah[i] += hv.x*whv.x + hv.y*whv.y + hv.z*whv.z + hv.w*whv.w;
            }
        }
        float bi = b_ih[j], bh = b_hh[j];
#pragma unroll
        for (int i = 0; i < 8; i++){
            gx[i*384 + j] = ax[i] + bi;
            gh[i*384 + j] = ah[i] + bh;
        }
    }
    __syncthreads();
#pragma unroll
    for (int l = 0; l < 2; l++){
        int o = l*512 + tid; int i = o >> 7, jj = o & 127;
        float r  = 1.f/(1.f + expf(-(gx[i*384 + jj]       + gh[i*384 + jj])));
        float z  = 1.f/(1.f + expf(-(gx[i*384 + 128 + jj] + gh[i*384 + 128 + jj])));
        float nn = tanhf(gx[i*384 + 256 + jj] + r * gh[i*384 + 256 + jj]);
        sn[o] = (1.f - z)*nn + z*hs[o];
    }
    __syncthreads();
    {
        int w = tid >> 5, lane = tid & 31;
        if (w < 8){
            float4 x = *(float4*)&sn[w*DS + lane*4];
            float s  = x.x + x.y + x.z + x.w;
            float sq = x.x*x.x + x.y*x.y + x.z*x.z + x.w*x.w;
            s = warp_sum(s); sq = warp_sum(sq);
            float m = s * (1.f/DS);
            float var = sq * (1.f/DS) - m*m;
            float r = rsqrtf(var + 1e-5f);
            int e = lane*4;
            hl[w*DS + e+0] = (x.x-m)*r*lmg[e+0] + lmb[e+0];
            hl[w*DS + e+1] = (x.y-m)*r*lmg[e+1] + lmb[e+1];
            hl[w*DS + e+2] = (x.z-m)*r*lmg[e+2] + lmb[e+2];
            hl[w*DS + e+3] = (x.w-m)*r*lmg[e+3] + lmb[e+3];
        }
    }
    __syncthreads();
    {
        int m = tid & 255, half = tid >> 8;   // half: slots 0-3 / 4-7
        float acc[4] = {0,0,0,0};
#pragma unroll 4
        for (int d = 0; d < DS; d++){
            float w1 = W1[(size_t)d*MLPH + m];
#pragma unroll
            for (int i = 0; i < 4; i++) acc[i] += hl[(half*4 + i)*DS + d] * w1;
        }
        float c1 = b1[m];
#pragma unroll
        for (int i = 0; i < 4; i++){
            float h = acc[i] + c1;
            hid[(half*4 + i)*MLPH + m] = h / (1.f + expf(-h));   // silu
        }
    }
    __syncthreads();
    {
        int d = tid & 127, ig = tid >> 7;     // ig 0..3, each 2 slots
        float acc[2] = {0,0};
#pragma unroll 4
        for (int m = 0; m < MLPH; m++){
            float w2 = W2[(size_t)m*DS + d];
#pragma unroll
            for (int ii = 0; ii < 2; ii++) acc[ii] += hid[(ig*2 + ii)*MLPH + m] * w2;
        }
        float c2 = b2[d];
#pragma unroll
        for (int ii = 0; ii < 2; ii++){
            int i = ig*2 + ii;
            g_slots[b*1024 + i*DS + d] = sn[i*DS + d] + acc[ii] + c2;
        }
    }
}

// ---------------- kernel 10: greedy merge map (warp per batch) ----------------
__global__ void merge_map_kernel(float* __restrict__ mm_out){
    __shared__ float sn[NS][DS];
    __shared__ float sim[64];
    int b = blockIdx.x, lane = threadIdx.x;
#pragma unroll
    for (int s = 0; s < NS; s++){
        float4 v = *(const float4*)&g_slots[b*1024 + s*DS + lane*4];
        float sq = v.x*v.x + v.y*v.y + v.z*v.z + v.w*v.w;
        sq = warp_sum(sq);
        float invn = 1.f / fmaxf(sqrtf(sq), 1e-12f);
        int e = lane*4;
        sn[s][e+0] = v.x*invn; sn[s][e+1] = v.y*invn;
        sn[s][e+2] = v.z*invn; sn[s][e+3] = v.w*invn;
    }
    __syncwarp();
    for (int p = lane; p < 64; p += 32){
        int s1 = p >> 3, s2 = p & 7;
        float acc = 0.f;
        for (int e = 0; e < DS; e++) acc += sn[s1][e] * sn[s2][e];
        sim[p] = acc - (s1 == s2 ? 2.f : 0.f);
    }
    __syncwarp();
    if (lane == 0){
        int mt[8] = {0,1,2,3,4,5,6,7};
        for (int rd = 0; rd < NS; rd++){
            float best = -1e30f; int bi = 0;
            for (int idx = 0; idx < 64; idx++)
                if (sim[idx] > best){ best = sim[idx]; bi = idx; }
            int row = bi >> 3, col = bi & 7;
            if (best > 0.9f){
                int src = row > col ? row : col;
                int tgt = row < col ? row : col;
                mt[src] = tgt;
                for (int t = 0; t < 8; t++){ sim[src*8 + t] = -2.f; sim[t*8 + src] = -2.f; }
            }
        }
        for (int s = 0; s < NS; s++){
            g_map[b*NS + s] = mt[s];
            mm_out[b*NS + s] = (float)mt[s];
        }
    }
}

// ---------------- kernel 11: merged slots (segment mean) + raw out ----------------
__global__ void merged_kernel(float* __restrict__ merged_out, float* __restrict__ raw_out){
    int b = blockIdx.x, d = threadIdx.x;   // 128 threads
    int mp[8];
#pragma unroll
    for (int s = 0; s < 8; s++) mp[s] = g_map[b*NS + s];
    float rv[8];
#pragma unroll
    for (int s = 0; s < 8; s++){
        rv[s] = g_slots[b*1024 + s*DS + d];
        raw_out[b*1024 + s*DS + d] = rv[s];
    }
#pragma unroll
    for (int t = 0; t < 8; t++){
        float sum = 0.f, c = 0.f;
#pragma unroll
        for (int s = 0; s < 8; s++)
            if (mp[s] == t){ sum += rv[s]; c += 1.f; }
        merged_out[b*1024 + t*DS + d] = sum / fmaxf(c, 1.f);
    }
}

// ---------------- launcher ----------------
extern "C" void kernel_launch(void* const* d_in, const int* in_sizes, int n_in,
                              void* d_out, int out_size)
{
    const float* feat    = (const float*)d_in[0];
    const float* ln_in_g = (const float*)d_in[1];
    const float* ln_in_b = (const float*)d_in[2];
    const float* Wk      = (const float*)d_in[3];
    const float* Wv      = (const float*)d_in[4];
    const float* Wq      = (const float*)d_in[5];
    const float* ln_s_g  = (const float*)d_in[6];
    const float* ln_s_b  = (const float*)d_in[7];
    const float* W_ih    = (const float*)d_in[8];
    const float* W_hh    = (const float*)d_in[9];
    const float* b_ih    = (const float*)d_in[10];
    const float* b_hh    = (const float*)d_in[11];
    const float* ln_m_g  = (const float*)d_in[12];
    const float* ln_m_b  = (const float*)d_in[13];
    const float* W1      = (const float*)d_in[14];
    const float* b1      = (const float*)d_in[15];
    const float* W2      = (const float*)d_in[16];
    const float* b2      = (const float*)d_in[17];
    const float* slot_mu = (const float*)d_in[18];

    float* out        = (float*)d_out;
    float* merged_out = out;                               // [32,8,128]
    float* attn_out   = out + BATCH*NS*DS;                 // [32,8,4096]
    float* mm_out     = attn_out + (size_t)BATCH*NS*NTOK;  // [32,8]
    float* raw_out    = mm_out + BATCH*NS;                 // [32,8,128]

    // launch order: logits lands in the ncu-captured slot (#4)
    prep_w_kernel<<<4, 256>>>(ln_in_g, ln_in_b, Wk, Wv, Wq, slot_mu); // 1
    kv_gemm_kernel<<<dim3(2, MROWS/128), 256>>>(feat);                 // 2

    for (int it = 0; it < 3; it++){
        compute_q_kernel<<<BATCH, 256>>>(ln_s_g, ln_s_b);              // 3 (it0)
        logits_kernel<<<dim3(NT, BATCH), 256>>>(attn_out);             // 4 (it0) <- captured
        upd_partial_kernel<<<dim3(NT, BATCH), 512>>>(attn_out);
        slot_update_kernel<<<BATCH, 512>>>(W_ih, W_hh, b_ih, b_hh,
                                           ln_m_g, ln_m_b, W1, b1, W2, b2);
    }
    merge_map_kernel<<<BATCH, 32>>>(mm_out);
    merged_kernel<<<BATCH, 128>>>(merged_out, raw_out);
}

// round 17
// speedup vs baseline: 2.1364x; 1.1113x over previous
#include <cuda_runtime.h>
#include <math.h>
#include <stdint.h>

#define BATCH 32
#define NTOK 4096
#define DIN 384
#define DS 128
#define NS 8
#define MLPH 256
#define MROWS (BATCH*NTOK)
#define TILE_N 256
#define NT (NTOK/TILE_N)   /* 16 */
#define ATT_SCALE 0.08838834764831845f

typedef unsigned long long u64;

// ---------------- scratch (device globals; no allocation) ----------------
__device__ float g_k[MROWS*DS];          // 64 MB
__device__ float g_v[MROWS*DS];          // 64 MB
__device__ float g_Wk2[DIN*DS];          // gamma * Wk  [k][n]
__device__ float g_Wv2[DIN*DS];          // gamma * Wv  [k][n]
__device__ float g_WqT[DS*DS];           // Wq transposed [d][e]
__device__ float g_bk[DS];               // beta @ Wk
__device__ float g_bv[DS];               // beta @ Wv
__device__ float g_slots[BATCH*NS*DS];
__device__ float g_q[BATCH*NS*DS];
__device__ float g_psum[BATCH*NT*NS];
__device__ float g_pupd[BATCH*NT*NS*DS];
__device__ int   g_map[BATCH*NS];

__device__ __forceinline__ float warp_sum(float v){
#pragma unroll
    for (int o = 16; o; o >>= 1) v += __shfl_xor_sync(0xffffffffu, v, o);
    return v;
}

// packed dual-fp32 FMA: d = a*b + c elementwise on (lo,hi) f32 pairs
__device__ __forceinline__ u64 ffma2(u64 a, u64 b, u64 c){
    u64 d;
    asm("fma.rn.f32x2 %0, %1, %2, %3;" : "=l"(d) : "l"(a), "l"(b), "l"(c));
    return d;
}
union F2 { u64 u; float2 f; };
__device__ __forceinline__ u64 fpack(float x){ F2 t; t.f.x = x; t.f.y = x; return t.u; }

// ---------------- kernel 0: prep weights + init slots (grid 4) ----------------
__global__ void prep_w_kernel(const float* __restrict__ lng, const float* __restrict__ lnb,
                              const float* __restrict__ Wk,  const float* __restrict__ Wv,
                              const float* __restrict__ Wq,  const float* __restrict__ mu){
    int tid = threadIdx.x;  // 256
    if (blockIdx.x == 3){   // init slots from mu
        for (int i = tid; i < BATCH*NS*DS; i += 256)
            g_slots[i] = mu[i & (DS-1)];
        return;
    }
    if (blockIdx.x == 2){   // Wq transpose: WqT[d][e] = Wq[e][d]
        for (int i = tid; i < DS*DS; i += 256){
            int d = i >> 7, e = i & 127;
            g_WqT[d*DS + e] = Wq[e*DS + d];
        }
        return;
    }
    const float* W  = blockIdx.x ? Wv : Wk;
    float* Wo       = blockIdx.x ? g_Wv2 : g_Wk2;
    float* bo       = blockIdx.x ? g_bv  : g_bk;
    for (int i = tid; i < DIN*DS; i += 256){
        int k = i >> 7;
        Wo[i] = lng[k] * W[i];
    }
    __shared__ float part[2][DS];
    int n = tid & 127, half = tid >> 7;
    float acc = 0.f;
    for (int k = half*192; k < half*192 + 192; k++)
        acc += lnb[k] * W[k*DS + n];
    part[half][n] = acc;
    __syncthreads();
    if (tid < DS) bo[tid] = part[0][tid] + part[1][tid];
}

// ---------------- kernel 1: fused LN + K/V GEMM, conflict-free f32x2 --------
#define BKK 8
__global__ void __launch_bounds__(256,2) kv_gemm_kernel(const float* __restrict__ feat)
{
    __shared__ __align__(16) float As[2][BKK][132];
    __shared__ __align__(16) float Bs[2][BKK][128];
    __shared__ float sMean[128], sRstd[128];

    const float* W    = (blockIdx.x == 0) ? g_Wk2 : g_Wv2;
    const float* bias = (blockIdx.x == 0) ? g_bk  : g_bv;
    float* out        = (blockIdx.x == 0) ? g_k   : g_v;
    int row0 = blockIdx.y * 128;
    int tid = threadIdx.x;
    int wid = tid >> 5, lane = tid & 31;

    for (int r = wid; r < 128; r += 8){
        const float* p = feat + (size_t)(row0 + r) * DIN;
        float s = 0.f, sq = 0.f;
#pragma unroll
        for (int c = 0; c < 3; c++){
            float4 v = *(const float4*)(p + lane*4 + c*128);
            s  += v.x + v.y + v.z + v.w;
            sq += v.x*v.x + v.y*v.y + v.z*v.z + v.w*v.w;
        }
        s = warp_sum(s); sq = warp_sum(sq);
        if (lane == 0){
            float m = s * (1.f/DIN);
            float var = sq * (1.f/DIN) - m*m;
            sMean[r] = m;
            sRstd[r] = rsqrtf(var + 1e-5f);
        }
    }
    __syncthreads();

    int arow = tid >> 1, kc0 = (tid & 1) * 4;
    float mean = sMean[arow];
    float rstd = sRstd[arow];
    const float* aptr = feat + (size_t)(row0 + arow) * DIN + kc0;
    int bk = tid >> 5, bn = (lane) * 4;

    int mb = (wid >> 1) * 32 + (lane >> 3) * 8;
    int nb = (wid & 1) * 64 + (lane & 7) * 4;

    u64 acc[8][4];
#pragma unroll
    for (int i = 0; i < 8; i++)
#pragma unroll
        for (int j = 0; j < 4; j++) acc[i][j] = 0ULL;

    float4 aA, bW;
    auto loadg = [&](int k0){
        aA = *(const float4*)(aptr + k0);
        bW = *(const float4*)(W + (size_t)(k0 + bk)*DS + bn);
    };
    auto stores = [&](int buf){
        As[buf][kc0+0][arow] = (aA.x - mean) * rstd;
        As[buf][kc0+1][arow] = (aA.y - mean) * rstd;
        As[buf][kc0+2][arow] = (aA.z - mean) * rstd;
        As[buf][kc0+3][arow] = (aA.w - mean) * rstd;
        *(float4*)&Bs[buf][bk][bn] = bW;
    };

    loadg(0); stores(0); __syncthreads();
    const int nk = DIN / BKK;   // 48
    for (int t = 0; t < nk; t++){
        int cur = t & 1;
        if (t + 1 < nk) loadg((t+1)*BKK);
#pragma unroll
        for (int k = 0; k < BKK; k++){
            float4 a0 = *(const float4*)&As[cur][k][mb];
            float4 a1 = *(const float4*)&As[cur][k][mb+4];
            ulonglong2 B0 = *(const ulonglong2*)&Bs[cur][k][nb];
            ulonglong2 B1 = *(const ulonglong2*)&Bs[cur][k][nb+32];
            u64 bp0 = B0.x, bp1 = B0.y, bp2 = B1.x, bp3 = B1.y;
            float av[8] = {a0.x,a0.y,a0.z,a0.w,a1.x,a1.y,a1.z,a1.w};
#pragma unroll
            for (int i = 0; i < 8; i++){
                u64 ap = fpack(av[i]);
                acc[i][0] = ffma2(ap, bp0, acc[i][0]);
                acc[i][1] = ffma2(ap, bp1, acc[i][1]);
                acc[i][2] = ffma2(ap, bp2, acc[i][2]);
                acc[i][3] = ffma2(ap, bp3, acc[i][3]);
            }
        }
        if (t + 1 < nk){ stores((t+1)&1); __syncthreads(); }
    }

    float4 bv0 = *(const float4*)&bias[nb];
    float4 bv1 = *(const float4*)&bias[nb+32];
#pragma unroll
    for (int i = 0; i < 8; i++){
        int r = row0 + mb + i;
        F2 c0, c1, c2, c3;
        c0.u = acc[i][0]; c1.u = acc[i][1]; c2.u = acc[i][2]; c3.u = acc[i][3];
        float* op = out + (size_t)r * DS;
        *(float4*)(op + nb)      = make_float4(c0.f.x+bv0.x, c0.f.y+bv0.y, c1.f.x+bv0.z, c1.f.y+bv0.w);
        *(float4*)(op + nb + 32) = make_float4(c2.f.x+bv1.x, c2.f.y+bv1.y, c3.f.x+bv1.z, c3.f.y+bv1.w);
    }
}

// ---------------- kernel 4: LN(slots) @ Wq (vectorized via WqT) -------------
__global__ void compute_q_kernel(const float* __restrict__ gg,
                                 const float* __restrict__ bb){
    __shared__ float sl[NS][DS];
    __shared__ float sn[NS][DS];
    int b = blockIdx.x, tid = threadIdx.x;
#pragma unroll
    for (int l = 0; l < 4; l++){
        int o = l*256 + tid;
        sl[o>>7][o&127] = g_slots[b*NS*DS + o];
    }
    __syncthreads();
    int w = tid >> 5, lane = tid & 31;
    {
        float4 x = *(float4*)&sl[w][lane*4];
        float s  = x.x + x.y + x.z + x.w;
        float sq = x.x*x.x + x.y*x.y + x.z*x.z + x.w*x.w;
        s = warp_sum(s); sq = warp_sum(sq);
        float m = s * (1.f/DS);
        float var = sq * (1.f/DS) - m*m;
        float r = rsqrtf(var + 1e-5f);
        int e = lane*4;
        sn[w][e+0] = (x.x-m)*r*gg[e+0] + bb[e+0];
        sn[w][e+1] = (x.y-m)*r*gg[e+1] + bb[e+1];
        sn[w][e+2] = (x.z-m)*r*gg[e+2] + bb[e+2];
        sn[w][e+3] = (x.w-m)*r*gg[e+3] + bb[e+3];
    }
    __syncthreads();
#pragma unroll
    for (int l = 0; l < 4; l++){
        int o = l*256 + tid; int s = o >> 7, d = o & 127;
        const float4* wp = (const float4*)&g_WqT[d*DS];
        const float4* sp = (const float4*)&sn[s][0];
        float acc = 0.f;
#pragma unroll
        for (int e4 = 0; e4 < 32; e4++){
            float4 wv = wp[e4], xv = sp[e4];
            acc += wv.x*xv.x + wv.y*xv.y + wv.z*xv.z + wv.w*xv.w;
        }
        g_q[b*NS*DS + o] = acc;
    }
}

// ---------------- kernel 5: logits v1 @ TILE_N=256 (grid 512) ---------------
__global__ void __launch_bounds__(256) logits_kernel(float* __restrict__ attn_out){
    __shared__ float at[NS][TILE_N];
    __shared__ float wsum[8][NS];
    int nt = blockIdx.x, b = blockIdx.y;
    int tid = threadIdx.x, w = tid >> 5, lane = tid & 31;
    int n0 = nt * TILE_N;
    float4 q[NS];
#pragma unroll
    for (int s = 0; s < NS; s++)
        q[s] = *(const float4*)&g_q[(b*NS + s)*DS + lane*4];
    float rs[NS] = {0,0,0,0,0,0,0,0};
    for (int j = 0; j < TILE_N/8; j++){         // 32 tokens per warp
        int n = n0 + w*(TILE_N/8) + j;
        float4 kv = *(const float4*)&g_k[(size_t)(b*NTOK + n)*DS + lane*4];
        float p[NS];
#pragma unroll
        for (int s = 0; s < NS; s++)
            p[s] = kv.x*q[s].x + kv.y*q[s].y + kv.z*q[s].z + kv.w*q[s].w;
#pragma unroll
        for (int o = 16; o; o >>= 1)
#pragma unroll
            for (int s = 0; s < NS; s++) p[s] += __shfl_xor_sync(0xffffffffu, p[s], o);
        float mx = -1e30f;
#pragma unroll
        for (int s = 0; s < NS; s++){ p[s] *= ATT_SCALE; mx = fmaxf(mx, p[s]); }
        float tot = 0.f;
#pragma unroll
        for (int s = 0; s < NS; s++){ p[s] = expf(p[s] - mx); tot += p[s]; }
        float itot = 1.f / tot;
#pragma unroll
        for (int s = 0; s < NS; s++){
            float a = p[s] * itot;
            rs[s] += a;
            if (lane == s) at[s][w*(TILE_N/8) + j] = a;
        }
    }
    if (lane == 0){
#pragma unroll
        for (int s = 0; s < NS; s++) wsum[w][s] = rs[s];
    }
    __syncthreads();
    if (tid < NS){
        float acc = 0.f;
#pragma unroll
        for (int ww = 0; ww < 8; ww++) acc += wsum[ww][tid];
        g_psum[(b*NT + nt)*NS + tid] = acc;
    }
#pragma unroll
    for (int l = 0; l < 8; l++){                // 8*256 = 2048 = NS*TILE_N
        int o = l*256 + tid; int s = o >> 8, jj = o & 255;
        attn_out[(size_t)(b*NS + s)*NTOK + n0 + jj] = at[s][jj];
    }
}

// ---------------- kernel 7: partial updates (512 thr, TILE_N=256) -----------
__global__ void __launch_bounds__(512) upd_partial_kernel(const float* __restrict__ attn_out){
    __shared__ float at[NS][TILE_N];
    __shared__ float inv[NS];
    __shared__ float p2[NT*NS];                 // 128
    int nt = blockIdx.x, b = blockIdx.y, tid = threadIdx.x;
    int n0 = nt * TILE_N;
    if (tid < NT*NS) p2[tid] = g_psum[b*NT*NS + tid];
    __syncthreads();
    if (tid < NS){
        float a = 0.f;
#pragma unroll
        for (int q = 0; q < NT; q++) a += p2[q*NS + tid];
        inv[tid] = 1.f / (a + 1e-8f);
    }
    __syncthreads();
#pragma unroll
    for (int l = 0; l < 4; l++){                // 4*512 = 2048
        int o = l*512 + tid; int s = o >> 8, jj = o & 255;
        at[s][jj] = attn_out[(size_t)(b*NS + s)*NTOK + n0 + jj] * inv[s];
    }
    __syncthreads();
    int d = tid & 127, sg = tid >> 7;           // sg 0..3, 2 slots each
    float acc0 = 0.f, acc1 = 0.f;
    const float* vp = g_v + (size_t)(b*NTOK + n0)*DS + d;
#pragma unroll 8
    for (int n = 0; n < TILE_N; n++){
        float vv = vp[(size_t)n*DS];
        acc0 += at[sg*2    ][n] * vv;
        acc1 += at[sg*2 + 1][n] * vv;
    }
    g_pupd[((b*NT + nt)*NS + sg*2    )*DS + d] = acc0;
    g_pupd[((b*NT + nt)*NS + sg*2 + 1)*DS + d] = acc1;
}

// ---------------- kernel 9: GRU + LN + MLP residual (512 threads) -----------
__global__ void __launch_bounds__(512) slot_update_kernel(
    const float* __restrict__ W_ih, const float* __restrict__ W_hh,
    const float* __restrict__ b_ih, const float* __restrict__ b_hh,
    const float* __restrict__ lmg,  const float* __restrict__ lmb,
    const float* __restrict__ W1,   const float* __restrict__ b1,
    const float* __restrict__ W2,   const float* __restrict__ b2)
{
    __shared__ float buf[9216];
    float* xs  = buf;            // [8][128] updates
    float* hs  = buf + 1024;     // [8][128] prev slots
    float* gx  = buf + 2048;     // [8][384]
    float* gh  = buf + 5120;     // [8][384]
    float* sn  = buf + 8192;     // [8][128] post-GRU slots
    float* hl  = buf;            // reuse xs: LN output [8][128]
    float* hid = buf + 2048;     // reuse gx: MLP hidden [8][256]
    int b = blockIdx.x, tid = threadIdx.x;
#pragma unroll
    for (int l = 0; l < 2; l++){
        int o = l*512 + tid;
        float a = 0.f;
#pragma unroll
        for (int q = 0; q < NT; q++) a += g_pupd[(b*NT + q)*1024 + o];
        xs[o] = a;
        hs[o] = g_slots[b*1024 + o];
    }
    __syncthreads();
    if (tid < 384){
        int j = tid;
        float ax[8] = {0,0,0,0,0,0,0,0};
        float ah[8] = {0,0,0,0,0,0,0,0};
        const float4* wx = (const float4*)(W_ih + (size_t)j*DS);
        const float4* wh = (const float4*)(W_hh + (size_t)j*DS);
#pragma unroll 8
        for (int d4 = 0; d4 < 32; d4++){
            float4 wxv = wx[d4], whv = wh[d4];
            int d = d4*4;
#pragma unroll
            for (int i = 0; i < 8; i++){
                float4 xv = *(const float4*)&xs[i*DS + d];
                float4 hv = *(const float4*)&hs[i*DS + d];
                ax[i] += xv.x*wxv.x + xv.y*wxv.y + xv.z*wxv.z + xv.w*wxv.w;
                ah[i] += hv.x*whv.x + hv.y*whv.y + hv.z*whv.z + hv.w*whv.w;
            }
        }
        float bi = b_ih[j], bh = b_hh[j];
#pragma unroll
        for (int i = 0; i < 8; i++){
            gx[i*384 + j] = ax[i] + bi;
            gh[i*384 + j] = ah[i] + bh;
        }
    }
    __syncthreads();
#pragma unroll
    for (int l = 0; l < 2; l++){
        int o = l*512 + tid; int i = o >> 7, jj = o & 127;
        float r  = 1.f/(1.f + expf(-(gx[i*384 + jj]       + gh[i*384 + jj])));
        float z  = 1.f/(1.f + expf(-(gx[i*384 + 128 + jj] + gh[i*384 + 128 + jj])));
        float nn = tanhf(gx[i*384 + 256 + jj] + r * gh[i*384 + 256 + jj]);
        sn[o] = (1.f - z)*nn + z*hs[o];
    }
    __syncthreads();
    {
        int w = tid >> 5, lane = tid & 31;
        if (w < 8){
            float4 x = *(float4*)&sn[w*DS + lane*4];
            float s  = x.x + x.y + x.z + x.w;
            float sq = x.x*x.x + x.y*x.y + x.z*x.z + x.w*x.w;
            s = warp_sum(s); sq = warp_sum(sq);
            float m = s * (1.f/DS);
            float var = sq * (1.f/DS) - m*m;
            float r = rsqrtf(var + 1e-5f);
            int e = lane*4;
            hl[w*DS + e+0] = (x.x-m)*r*lmg[e+0] + lmb[e+0];
            hl[w*DS + e+1] = (x.y-m)*r*lmg[e+1] + lmb[e+1];
            hl[w*DS + e+2] = (x.z-m)*r*lmg[e+2] + lmb[e+2];
            hl[w*DS + e+3] = (x.w-m)*r*lmg[e+3] + lmb[e+3];
        }
    }
    __syncthreads();
    {
        int m = tid & 255, half = tid >> 8;   // half: slots 0-3 / 4-7
        float acc[4] = {0,0,0,0};
#pragma unroll 4
        for (int d = 0; d < DS; d++){
            float w1 = W1[(size_t)d*MLPH + m];
#pragma unroll
            for (int i = 0; i < 4; i++) acc[i] += hl[(half*4 + i)*DS + d] * w1;
        }
        float c1 = b1[m];
#pragma unroll
        for (int i = 0; i < 4; i++){
            float h = acc[i] + c1;
            hid[(half*4 + i)*MLPH + m] = h / (1.f + expf(-h));   // silu
        }
    }
    __syncthreads();
    {
        int d = tid & 127, ig = tid >> 7;     // ig 0..3, each 2 slots
        float acc[2] = {0,0};
#pragma unroll 4
        for (int m = 0; m < MLPH; m++){
            float w2 = W2[(size_t)m*DS + d];
#pragma unroll
            for (int ii = 0; ii < 2; ii++) acc[ii] += hid[(ig*2 + ii)*MLPH + m] * w2;
        }
        float c2 = b2[d];
#pragma unroll
        for (int ii = 0; ii < 2; ii++){
            int i = ig*2 + ii;
            g_slots[b*1024 + i*DS + d] = sn[i*DS + d] + acc[ii] + c2;
        }
    }
}

// ---------------- kernel 10: greedy merge map (warp per batch) ----------------
__global__ void merge_map_kernel(float* __restrict__ mm_out){
    __shared__ float sn[NS][DS];
    __shared__ float sim[64];
    int b = blockIdx.x, lane = threadIdx.x;
#pragma unroll
    for (int s = 0; s < NS; s++){
        float4 v = *(const float4*)&g_slots[b*1024 + s*DS + lane*4];
        float sq = v.x*v.x + v.y*v.y + v.z*v.z + v.w*v.w;
        sq = warp_sum(sq);
        float invn = 1.f / fmaxf(sqrtf(sq), 1e-12f);
        int e = lane*4;
        sn[s][e+0] = v.x*invn; sn[s][e+1] = v.y*invn;
        sn[s][e+2] = v.z*invn; sn[s][e+3] = v.w*invn;
    }
    __syncwarp();
    for (int p = lane; p < 64; p += 32){
        int s1 = p >> 3, s2 = p & 7;
        float acc = 0.f;
        for (int e = 0; e < DS; e++) acc += sn[s1][e] * sn[s2][e];
        sim[p] = acc - (s1 == s2 ? 2.f : 0.f);
    }
    __syncwarp();
    if (lane == 0){
        int mt[8] = {0,1,2,3,4,5,6,7};
        for (int rd = 0; rd < NS; rd++){
            float best = -1e30f; int bi = 0;
            for (int idx = 0; idx < 64; idx++)
                if (sim[idx] > best){ best = sim[idx]; bi = idx; }
            int row = bi >> 3, col = bi & 7;
            if (best > 0.9f){
                int src = row > col ? row : col;
                int tgt = row < col ? row : col;
                mt[src] = tgt;
                for (int t = 0; t < 8; t++){ sim[src*8 + t] = -2.f; sim[t*8 + src] = -2.f; }
            }
        }
        for (int s = 0; s < NS; s++){
            g_map[b*NS + s] = mt[s];
            mm_out[b*NS + s] = (float)mt[s];
        }
    }
}

// ---------------- kernel 11: merged slots (segment mean) + raw out ----------------
__global__ void merged_kernel(float* __restrict__ merged_out, float* __restrict__ raw_out){
    int b = blockIdx.x, d = threadIdx.x;   // 128 threads
    int mp[8];
#pragma unroll
    for (int s = 0; s < 8; s++) mp[s] = g_map[b*NS + s];
    float rv[8];
#pragma unroll
    for (int s = 0; s < 8; s++){
        rv[s] = g_slots[b*1024 + s*DS + d];
        raw_out[b*1024 + s*DS + d] = rv[s];
    }
#pragma unroll
    for (int t = 0; t < 8; t++){
        float sum = 0.f, c = 0.f;
#pragma unroll
        for (int s = 0; s < 8; s++)
            if (mp[s] == t){ sum += rv[s]; c += 1.f; }
        merged_out[b*1024 + t*DS + d] = sum / fmaxf(c, 1.f);
    }
}

// ---------------- launcher ----------------
extern "C" void kernel_launch(void* const* d_in, const int* in_sizes, int n_in,
                              void* d_out, int out_size)
{
    const float* feat    = (const float*)d_in[0];
    const float* ln_in_g = (const float*)d_in[1];
    const float* ln_in_b = (const float*)d_in[2];
    const float* Wk      = (const float*)d_in[3];
    const float* Wv      = (const float*)d_in[4];
    const float* Wq      = (const float*)d_in[5];
    const float* ln_s_g  = (const float*)d_in[6];
    const float* ln_s_b  = (const float*)d_in[7];
    const float* W_ih    = (const float*)d_in[8];
    const float* W_hh    = (const float*)d_in[9];
    const float* b_ih    = (const float*)d_in[10];
    const float* b_hh    = (const float*)d_in[11];
    const float* ln_m_g  = (const float*)d_in[12];
    const float* ln_m_b  = (const float*)d_in[13];
    const float* W1      = (const float*)d_in[14];
    const float* b1      = (const float*)d_in[15];
    const float* W2      = (const float*)d_in[16];
    const float* b2      = (const float*)d_in[17];
    const float* slot_mu = (const float*)d_in[18];

    float* out        = (float*)d_out;
    float* merged_out = out;                               // [32,8,128]
    float* attn_out   = out + BATCH*NS*DS;                 // [32,8,4096]
    float* mm_out     = attn_out + (size_t)BATCH*NS*NTOK;  // [32,8]
    float* raw_out    = mm_out + BATCH*NS;                 // [32,8,128]

    // launch order: logits lands in the ncu-captured slot (#4)
    prep_w_kernel<<<4, 256>>>(ln_in_g, ln_in_b, Wk, Wv, Wq, slot_mu); // 1
    kv_gemm_kernel<<<dim3(2, MROWS/128), 256>>>(feat);                 // 2

    for (int it = 0; it < 3; it++){
        compute_q_kernel<<<BATCH, 256>>>(ln_s_g, ln_s_b);              // 3 (it0)
        logits_kernel<<<dim3(NT, BATCH), 256>>>(attn_out);             // 4 (it0) <- captured
        upd_partial_kernel<<<dim3(NT, BATCH), 512>>>(attn_out);
        slot_update_kernel<<<BATCH, 512>>>(W_ih, W_hh, b_ih, b_hh,
                                           ln_m_g, ln_m_b, W1, b1, W2, b2);
    }
    merge_map_kernel<<<BATCH, 32>>>(mm_out);
    merged_kernel<<<BATCH, 128>>>(merged_out, raw_out);
}